// round 14
// baseline (speedup 1.0000x reference)
#include <cuda_runtime.h>
#include <cuda_bf16.h>
#include <cuda_fp16.h>
#include <math.h>
#include <stdint.h>

#define Bq 8
#define Sq 12
#define Nq 4096
#define Fq 4
#define Hq 64
#define CHW 68                    // F + H
#define NCOL 544                  // logical diffusion cols (b*68+f)
#define AST 1024                  // g_a row stride (fp16): b*128+f, pads zero
#define NPAD 576                  // padded B columns
#define NH  (Nq*Hq)               // 262144
#define N3H (Nq*3*Hq)             // 786432
#define ZOUT ((size_t)Bq*NH)      // offset of recon in output
#define ASCALE 2048.0f
#define AINV   (1.0f/2048.0f)

// -------- persistent scratch (device globals; no allocation) --------
__device__ float g_h[Bq*NH];                        // h_last only (written at t=11)
__device__ __align__(16) __half g_a[(size_t)Nq*AST]; // diffusion out fp16 [m][b*128+f]
__device__ __align__(16) __half g_gate[Bq*N3H];     // sigmoid(gc1) torch-flat, fp16
__device__ __align__(16) __half g_tconv[Bq*NH];     // tanh(gc2), fp16
__device__ __align__(16) __half g_ah[(size_t)Nq*Nq];           // adj*2^11 (fp16)
__device__ __align__(16) __half g_bh[(size_t)Nq*NPAD];         // catT fp16 [k][col]
__device__ __align__(16) __half g_w[80*256];                   // W1|W2 fp16 [k][ch]
// decoder fp16 weights (column-permuted: col = hc*4 + gate)
__device__ __align__(16) __half g_dwih[64*256];
__device__ __align__(16) __half g_dwhh[64*256];
__device__ __align__(16) __half g_d1[64*32];
__device__ float g_dbb[256];                        // permuted b_ih+b_hh

__device__ __forceinline__ float sigf(float x){ return 1.f/(1.f+expf(-x)); }

// ---- warp MMA helpers ----
__device__ __forceinline__ uint32_t smem_u32(const void* p) {
    uint32_t a;
    asm("{ .reg .u64 t; cvta.to.shared.u64 t, %1; cvt.u32.u64 %0, t; }"
        : "=r"(a) : "l"(p));
    return a;
}
__device__ __forceinline__ void cpasync16(uint32_t dst, const void* src){
    asm volatile("cp.async.cg.shared.global [%0], [%1], 16;"
                 :: "r"(dst), "l"(src) : "memory");
}
__device__ __forceinline__ void ldsm4(uint32_t r[4], uint32_t addr){
    asm volatile("ldmatrix.sync.aligned.m8n8.x4.shared.b16 {%0,%1,%2,%3}, [%4];"
                 : "=r"(r[0]), "=r"(r[1]), "=r"(r[2]), "=r"(r[3]) : "r"(addr));
}
__device__ __forceinline__ void ldsm4t(uint32_t r[4], uint32_t addr){
    asm volatile("ldmatrix.sync.aligned.m8n8.x4.trans.shared.b16 {%0,%1,%2,%3}, [%4];"
                 : "=r"(r[0]), "=r"(r[1]), "=r"(r[2]), "=r"(r[3]) : "r"(addr));
}
// fp16 MMA
__device__ __forceinline__ void mma16816h(float d[4], const uint32_t a[4],
                                          uint32_t b0, uint32_t b1){
    asm volatile(
        "mma.sync.aligned.m16n8k16.row.col.f32.f16.f16.f32 "
        "{%0,%1,%2,%3}, {%4,%5,%6,%7}, {%8,%9}, {%0,%1,%2,%3};"
        : "+f"(d[0]), "+f"(d[1]), "+f"(d[2]), "+f"(d[3])
        : "r"(a[0]), "r"(a[1]), "r"(a[2]), "r"(a[3]), "r"(b0), "r"(b1));
}

// ===================== one-time prep (3 kernels; k_mma is launch #4) =====================
__global__ void k_prep_adj(const float* __restrict__ adj){
    size_t i = (size_t)blockIdx.x*256 + threadIdx.x;   // Nq*Nq exactly
    g_ah[i] = __float2half_rn(adj[i] * ASCALE);
}

__global__ void k_prep_w(const float* __restrict__ W1, const float* __restrict__ W2,
                         const float* __restrict__ W_ih, const float* __restrict__ W_hh,
                         const float* __restrict__ b_ih, const float* __restrict__ b_hh,
                         const float* __restrict__ D1){
    if(blockIdx.x < 80){
        int idx = blockIdx.x*256 + threadIdx.x;
        int f = idx >> 8, ch = idx & 255;
        float v = 0.f;
        if(f < 68) v = (ch < 192) ? W1[f*192 + ch] : W2[f*64 + ch - 192];
        g_w[idx] = __float2half_rn(v);
    } else {
        int idx = (blockIdx.x - 80)*256 + threadIdx.x;  // 64*256
        int k = idx >> 8, c = idx & 255;
        int hc = c >> 2, gate = c & 3;
        g_dwih[idx] = __float2half_rn(W_ih[(gate*64 + hc)*64 + k]);
        g_dwhh[idx] = __float2half_rn(W_hh[(gate*64 + hc)*64 + k]);
        if(idx < 64*32) g_d1[idx] = __float2half_rn(D1[idx]);
        if(idx < 256){
            int g2 = idx & 3, h2 = idx >> 2;
            g_dbb[idx] = b_ih[g2*64 + h2] + b_hh[g2*64 + h2];
        }
    }
}

__global__ void k_prep_bh(const float* __restrict__ se, const float* __restrict__ X){
    if(blockIdx.x < NH/256){
        int j = blockIdx.x*256 + threadIdx.x;   // NH exactly
        int n = j >> 6, hc = j & 63;
        __half hv = __float2half_rn(se[j]);
        #pragma unroll
        for(int b=0;b<Bq;b++)
            g_bh[(size_t)n*NPAD + b*CHW + 4 + hc] = hv;
    } else {
        int i = (blockIdx.x - NH/256)*256 + threadIdx.x;   // 32*4096 exactly
        int b = i >> 14, f = (i >> 12) & 3, k = i & 4095;
        float v = X[(size_t)(b*Sq*Nq + k)*Fq + f];  // t = 0
        g_bh[(size_t)k*NPAD + b*CHW + f] = __float2half_rn(v);
    }
}

// ===================== HMMA GEMM (encoder diffusion, fp16, BN=96) =====================
// BM=128, BN=96, BK=32, 4-stage cp.async, 2 CTAs/SM, 256 thr, warp 4m x 2n (tile 32x48).
#define MSTAGE 16384
#define MA_OFF 0
#define MB_OFF 8192

__device__ __forceinline__ void mma_load_stage(uint32_t dbase, int s, int kt,
                                               int m0, int n0, int tid){
    const uint32_t sb = dbase + (uint32_t)s*MSTAGE;
    const int k0 = kt*32;
    // A: 128 rows x 4 chunks(16B) = 512
    #pragma unroll
    for(int it=0; it<2; it++){
        int i = tid + it*256;
        int row = i >> 2, c = i & 3;
        const __half* src = g_ah + ((size_t)(m0+row) << 12) + k0 + c*8;
        uint32_t dst = sb + MA_OFF
            + (uint32_t)row*64 + (uint32_t)((c ^ ((row>>1)&3))<<4);
        cpasync16(dst, src);
    }
    // B: 32 k-rows x 12 chunks (iterated over 16-slot rows, guard c<12)
    #pragma unroll
    for(int it=0; it<2; it++){
        int i = tid + it*256;
        int row = i >> 4, c = i & 15;
        if(c < 12){
            const __half* src = g_bh + (size_t)(k0+row)*NPAD + n0 + c*8;
            uint32_t dst = sb + MB_OFF
                + (uint32_t)row*256 + (uint32_t)((c ^ (row&7))<<4);
            cpasync16(dst, src);
        }
    }
}

__global__ __launch_bounds__(256,2) void k_mma(){
    extern __shared__ char dyn[];
    const uint32_t dbase = smem_u32(dyn);
    const int tid = threadIdx.x;
    const int lane = tid & 31, wid = tid >> 5;
    const int warp_m = wid & 3, warp_n = wid >> 2;
    const int m0 = blockIdx.x * 128;
    const int n0 = blockIdx.y * 96;
    const int lrow = lane & 15, lhalf = lane >> 4;

    float acc[2][6][4];
    #pragma unroll
    for(int mt=0;mt<2;mt++)
        #pragma unroll
        for(int nt=0;nt<6;nt++)
            #pragma unroll
            for(int q=0;q<4;q++) acc[mt][nt][q] = 0.f;

    mma_load_stage(dbase, 0, 0, m0, n0, tid);
    asm volatile("cp.async.commit_group;" ::: "memory");
    mma_load_stage(dbase, 1, 1, m0, n0, tid);
    asm volatile("cp.async.commit_group;" ::: "memory");
    mma_load_stage(dbase, 2, 2, m0, n0, tid);
    asm volatile("cp.async.commit_group;" ::: "memory");

    for(int kt=0; kt<128; kt++){
        if(kt < 126)      { asm volatile("cp.async.wait_group 2;" ::: "memory"); }
        else if(kt == 126){ asm volatile("cp.async.wait_group 1;" ::: "memory"); }
        else              { asm volatile("cp.async.wait_group 0;" ::: "memory"); }
        __syncthreads();

        if(kt + 3 < 128){
            mma_load_stage(dbase, (kt+3)&3, kt+3, m0, n0, tid);
            asm volatile("cp.async.commit_group;" ::: "memory");
        }

        const uint32_t sb = dbase + (uint32_t)(kt&3)*MSTAGE;
        #pragma unroll
        for(int k16=0; k16<2; k16++){
            uint32_t ah[2][4];
            #pragma unroll
            for(int mt=0; mt<2; mt++){
                int row = warp_m*32 + mt*16 + lrow;
                int c = k16*2 + lhalf;
                uint32_t off = (uint32_t)row*64 + (uint32_t)((c ^ ((row>>1)&3))<<4);
                ldsm4(ah[mt], sb + MA_OFF + off);
            }
            uint32_t bh[3][4];
            #pragma unroll
            for(int nt16=0; nt16<3; nt16++){
                int k = k16*16 + lrow;
                int c = warp_n*6 + nt16*2 + lhalf;
                uint32_t off = (uint32_t)k*256 + (uint32_t)((c ^ (k&7))<<4);
                ldsm4t(bh[nt16], sb + MB_OFF + off);
            }
            #pragma unroll
            for(int mt=0; mt<2; mt++)
                #pragma unroll
                for(int nt16=0; nt16<3; nt16++)
                    #pragma unroll
                    for(int h8=0; h8<2; h8++){
                        mma16816h(acc[mt][nt16*2 + h8], ah[mt],
                                  bh[nt16][2*h8], bh[nt16][2*h8+1]);
                    }
        }
    }

    #pragma unroll
    for(int mt=0; mt<2; mt++){
        #pragma unroll
        for(int nt=0; nt<6; nt++){
            int col = n0 + warp_n*48 + nt*8 + (lane&3)*2;
            if(col < NCOL){
                int bb = col / 68, ff = col - bb*68;
                int colA = bb*128 + ff;                 // packed g_a layout
                int r0 = m0 + warp_m*32 + mt*16 + (lane>>2);
                __half2 h0 = __halves2half2(__float2half_rn(acc[mt][nt][0]*AINV),
                                            __float2half_rn(acc[mt][nt][1]*AINV));
                __half2 h1 = __halves2half2(__float2half_rn(acc[mt][nt][2]*AINV),
                                            __float2half_rn(acc[mt][nt][3]*AINV));
                *(__half2*)(g_a + (size_t)r0*AST + colA)     = h0;
                *(__half2*)(g_a + (size_t)(r0+8)*AST + colA) = h1;
            }
        }
    }
}

// ===================== gates GEMM + activations (fp16) =====================
#define GA_B 272
#define GW_B 272
#define GSM_A 0
#define GSM_W (128*GA_B)                    // 34816
#define GSM_BC (GSM_W + 80*GW_B)            // 56576
#define GSM_TOT (GSM_BC + 128*4)            // 57088

__global__ __launch_bounds__(256,2) void k_gates_mma(
        const float* __restrict__ b1, const float* __restrict__ b2){
    extern __shared__ char smg[];
    const uint32_t sb = smem_u32(smg);
    float* bc = (float*)(smg + GSM_BC);
    const int tid = threadIdx.x, lane = tid & 31, wid = tid >> 5;
    const int warp_m = wid & 3, warp_n = wid >> 2;
    const int m0 = blockIdx.x * 128;
    const int b  = blockIdx.y;
    const int z  = blockIdx.z;
    const int lrow = lane & 15, lhalf = lane >> 4;

    #pragma unroll
    for(int it=0; it<8; it++){
        int i = tid + it*256;
        int row = i >> 4, c = i & 15;
        const __half* src = g_a + (size_t)(m0+row)*AST + b*128 + c*8;
        cpasync16(sb + GSM_A + (uint32_t)row*GA_B + (uint32_t)c*16, src);
    }
    #pragma unroll
    for(int it=0; it<5; it++){
        int i = tid + it*256;
        int f = i >> 4, c = i & 15;
        const __half* src = g_w + f*256 + z*128 + c*8;
        cpasync16(sb + GSM_W + (uint32_t)f*GW_B + (uint32_t)c*16, src);
    }
    asm volatile("cp.async.commit_group;" ::: "memory");
    if(tid < 128){
        int ch = z*128 + tid;
        bc[tid] = (ch < 192) ? b1[ch] : b2[ch - 192];
    }
    asm volatile("cp.async.wait_group 0;" ::: "memory");
    __syncthreads();

    float acc[2][8][4];
    #pragma unroll
    for(int mt=0;mt<2;mt++)
        #pragma unroll
        for(int nt=0;nt<8;nt++)
            #pragma unroll
            for(int q=0;q<4;q++) acc[mt][nt][q] = 0.f;

    #pragma unroll
    for(int k16=0; k16<5; k16++){
        uint32_t ah[2][4];
        #pragma unroll
        for(int mt=0; mt<2; mt++){
            int row = warp_m*32 + mt*16 + lrow;
            uint32_t off = (uint32_t)row*GA_B + (uint32_t)(k16*32 + lhalf*16);
            ldsm4(ah[mt], sb + GSM_A + off);
        }
        uint32_t bh[4][4];
        #pragma unroll
        for(int nt16=0; nt16<4; nt16++){
            int k = k16*16 + lrow;
            uint32_t off = (uint32_t)k*GW_B
                + (uint32_t)(warp_n*128 + nt16*32 + lhalf*16);
            ldsm4t(bh[nt16], sb + GSM_W + off);
        }
        #pragma unroll
        for(int mt=0; mt<2; mt++)
            #pragma unroll
            for(int nt16=0; nt16<4; nt16++)
                #pragma unroll
                for(int h8=0; h8<2; h8++){
                    mma16816h(acc[mt][nt16*2 + h8], ah[mt],
                              bh[nt16][2*h8], bh[nt16][2*h8+1]);
                }
    }

    #pragma unroll
    for(int mt=0; mt<2; mt++){
        #pragma unroll
        for(int nt=0; nt<8; nt++){
            int col = warp_n*64 + nt*8 + (lane&3)*2;
            int ch  = z*128 + col;
            float bb0 = bc[col], bb1 = bc[col+1];
            int r0 = m0 + warp_m*32 + mt*16 + (lane>>2);
            #pragma unroll
            for(int hf=0; hf<2; hf++){
                int node = r0 + 8*hf;
                float v0 = acc[mt][nt][2*hf]   + bb0;
                float v1 = acc[mt][nt][2*hf+1] + bb1;
                if(ch < 192){
                    __half2 o = __halves2half2(__float2half_rn(sigf(v0)),
                                               __float2half_rn(sigf(v1)));
                    *(__half2*)(g_gate + (size_t)b*N3H + (size_t)node*192 + ch) = o;
                }else{
                    __half2 o = __halves2half2(__float2half_rn(tanhf(v0)),
                                               __float2half_rn(tanhf(v1)));
                    *(__half2*)(g_tconv + (size_t)b*NH + (size_t)node*64 + (ch-192)) = o;
                }
            }
        }
    }
}

// -------- fused: LSTM cell (2 elems/thread) + catT X cols for t+1; z-out at t=11 --------
#define CELL_BLOCKS ((Bq*NH)/512)
__global__ void k_cell_catx(const float* __restrict__ se, const float* __restrict__ X,
                            float* __restrict__ out, int t){
    if(blockIdx.x < CELL_BLOCKS){
        int idx = (blockIdx.x*256 + threadIdx.x)*2;   // even, covers Bq*NH
        int b = idx >> 18;
        int j = idx & (NH-1);
        const __half* gg = g_gate + (size_t)b*N3H;
        __half2 f2 = *(const __half2*)(gg + j);
        __half2 i2 = *(const __half2*)(gg + NH + j);
        __half2 o2 = *(const __half2*)(gg + 2*NH + j);
        __half2 t2 = *(const __half2*)(g_tconv + (size_t)b*NH + j);
        float2 se2 = *(const float2*)(se + j);
        float c0 = __low2float(f2)*se2.x  + __low2float(i2)*__low2float(t2);
        float c1 = __high2float(f2)*se2.y + __high2float(i2)*__high2float(t2);
        float h0 = __low2float(o2)  * tanhf(c0);
        float h1 = __high2float(o2) * tanhf(c1);
        int n = j >> 6, hc = j & 63;
        *(__half2*)(g_bh + (size_t)n*NPAD + b*CHW + 4 + hc) =
            __halves2half2(__float2half_rn(h0), __float2half_rn(h1));
        if(t == Sq-1){
            float2 hv; hv.x = h0; hv.y = h1;
            *(float2*)(g_h + idx) = hv;
            *(float2*)(out + idx) = hv;
        }
    } else {
        int i = (blockIdx.x - CELL_BLOCKS)*256 + threadIdx.x;  // 32*4096
        int b = i >> 14, f = (i >> 12) & 3, k = i & 4095;
        float v = X[(size_t)((b*Sq + t + 1)*Nq + k)*Fq + f];
        g_bh[(size_t)k*NPAD + b*CHW + f] = __float2half_rn(v);
    }
}

// ===================== MMA decoder (fp16, XG fp16, occ-2) =====================
#define DW_ST 264
#define DA_ST 72
#define DXH   264
#define DD_ST 40
#define DS_W  0
#define DS_A  (DS_W + 64*DW_ST*2)           // 33792
#define DS_XG (DS_A + 64*DA_ST*2)           // 43008
#define DS_D1 (DS_XG + 64*DXH*2)            // 76800
#define DS_RED (DS_D1 + 64*DD_ST*2)         // 81920
#define DS_BB  (DS_RED + 64*8*4)            // 83968
#define DS_B1  (DS_BB + 256*4)              // 84992
#define DS_D2  (DS_B1 + 32*4)               // 85120
#define DS_TOT (DS_D2 + 32*4)               // 85248

__device__ __forceinline__ void dec_gemm_k64(float acc[2][8][4], uint32_t sb,
        int wm, int wn, int lrow, int lhalf){
    #pragma unroll
    for(int k16=0;k16<4;k16++){
        uint32_t ah[2][4];
        #pragma unroll
        for(int mt=0;mt<2;mt++){
            int row = wm*32 + mt*16 + lrow;
            uint32_t off = (uint32_t)row*(DA_ST*2) + (uint32_t)(k16*32 + lhalf*16);
            ldsm4(ah[mt], sb + DS_A + off);
        }
        uint32_t bh[4][4];
        #pragma unroll
        for(int nt16=0;nt16<4;nt16++){
            int k = k16*16 + lrow;
            uint32_t off = (uint32_t)k*(DW_ST*2)
                + (uint32_t)(wn*128 + nt16*32 + lhalf*16);
            ldsm4t(bh[nt16], sb + DS_W + off);
        }
        #pragma unroll
        for(int mt=0;mt<2;mt++)
            #pragma unroll
            for(int nt16=0;nt16<4;nt16++)
                #pragma unroll
                for(int h8=0;h8<2;h8++){
                    mma16816h(acc[mt][nt16*2 + h8], ah[mt],
                              bh[nt16][2*h8], bh[nt16][2*h8+1]);
                }
    }
}

__global__ __launch_bounds__(256,2) void k_dec_mma(
        const float* __restrict__ bd1, const float* __restrict__ D2,
        const float* __restrict__ bd2, float* __restrict__ out)
{
    extern __shared__ char smd[];
    const uint32_t sb = smem_u32(smd);
    __half* WS = (__half*)(smd + DS_W);
    __half* AS = (__half*)(smd + DS_A);
    __half* XG = (__half*)(smd + DS_XG);
    __half* D1S16 = (__half*)(smd + DS_D1);
    float* RED = (float*)(smd + DS_RED);
    float* BB  = (float*)(smd + DS_BB);
    float* B1S = (float*)(smd + DS_B1);
    float* D2S = (float*)(smd + DS_D2);
    const int tid = threadIdx.x, lane = tid & 31, wid = tid >> 5;
    const int r0 = blockIdx.x * 64;
    const int lrow = lane & 15, lhalf = lane >> 4;
    const int q = lane & 3, rql = lane >> 2;
    const int wm = wid & 1, wn = wid >> 1;
    const int hm = wid >> 1, hn = wid & 1;

    for(int idx=tid; idx<64*64; idx+=256){
        int row = idx >> 6, k = idx & 63;
        AS[row*DA_ST + k] = __float2half_rn(g_h[(size_t)(r0+row)*64 + k]);
    }
    for(int idx=tid; idx<64*256; idx+=256){
        int k = idx >> 8, c = idx & 255;
        WS[k*DW_ST + c] = g_dwih[idx];
    }
    {
        const __half zh = __float2half_rn(0.f);
        for(int idx=tid; idx<64*DD_ST; idx+=256){
            int k = idx / DD_ST, c = idx - k*DD_ST;
            D1S16[idx] = (c < 32) ? g_d1[k*32 + c] : zh;
        }
    }
    if(tid < 256) BB[tid] = g_dbb[tid];
    if(tid < 32){ B1S[tid] = bd1[tid]; D2S[tid] = D2[tid]; }
    __syncthreads();

    {
        float acc[2][8][4];
        #pragma unroll
        for(int mt=0;mt<2;mt++)
            #pragma unroll
            for(int nt=0;nt<8;nt++){
                int c0 = wn*64 + nt*8 + q*2;
                acc[mt][nt][0] = BB[c0];   acc[mt][nt][1] = BB[c0+1];
                acc[mt][nt][2] = BB[c0];   acc[mt][nt][3] = BB[c0+1];
            }
        dec_gemm_k64(acc, sb, wm, wn, lrow, lhalf);
        #pragma unroll
        for(int mt=0;mt<2;mt++)
            #pragma unroll
            for(int nt=0;nt<8;nt++){
                int r = wm*32 + mt*16 + rql;
                int c0 = wn*64 + nt*8 + q*2;
                *(__half2*)(XG + r*DXH + c0) =
                    __halves2half2(__float2half_rn(acc[mt][nt][0]),
                                   __float2half_rn(acc[mt][nt][1]));
                *(__half2*)(XG + (r+8)*DXH + c0) =
                    __halves2half2(__float2half_rn(acc[mt][nt][2]),
                                   __float2half_rn(acc[mt][nt][3]));
            }
    }
    __syncthreads();
    for(int idx=tid; idx<64*256; idx+=256){
        int k = idx >> 8, c = idx & 255;
        WS[k*DW_ST + c] = g_dwhh[idx];
    }
    __syncthreads();

    float cst[2][8];
    #pragma unroll
    for(int mt=0;mt<2;mt++)
        #pragma unroll
        for(int nt=0;nt<8;nt++) cst[mt][nt] = 0.f;
    const float bd2v = bd2[0];

    for(int s=0; s<Sq; s++){
        float acc[2][8][4];
        #pragma unroll
        for(int mt=0;mt<2;mt++)
            #pragma unroll
            for(int nt=0;nt<8;nt++){
                int r = wm*32 + mt*16 + rql;
                int c0 = wn*64 + nt*8 + q*2;
                float2 lo = __half22float2(*(const __half2*)(XG + r*DXH + c0));
                float2 hi = __half22float2(*(const __half2*)(XG + (r+8)*DXH + c0));
                acc[mt][nt][0] = lo.x; acc[mt][nt][1] = lo.y;
                acc[mt][nt][2] = hi.x; acc[mt][nt][3] = hi.y;
            }
        if(s > 0) dec_gemm_k64(acc, sb, wm, wn, lrow, lhalf);
        __syncthreads();

        #pragma unroll
        for(int mt=0;mt<2;mt++){
            #pragma unroll
            for(int nt=0;nt<8;nt++){
                float d0 = acc[mt][nt][0], d1 = acc[mt][nt][1];
                float d2 = acc[mt][nt][2], d3 = acc[mt][nt][3];
                float e0 = __shfl_xor_sync(0xffffffffu, d0, 1);
                float e1 = __shfl_xor_sync(0xffffffffu, d1, 1);
                float e2 = __shfl_xor_sync(0xffffffffu, d2, 1);
                float e3 = __shfl_xor_sync(0xffffffffu, d3, 1);
                float iv, fv, gv, ov;
                if((lane & 1) == 0){ iv = d0; fv = d1; gv = e0; ov = e1; }
                else               { iv = e2; fv = e3; gv = d2; ov = d3; }
                float cc = sigf(fv)*cst[mt][nt] + sigf(iv)*tanhf(gv);
                cst[mt][nt] = cc;
                float hh = sigf(ov)*tanhf(cc);
                int row = wm*32 + mt*16 + rql + ((lane & 1) << 3);
                int hc  = wn*16 + nt*2 + (q >> 1);
                AS[row*DA_ST + hc] = __float2half_rn(hh);
            }
        }
        __syncthreads();

        float u[2][4];
        #pragma unroll
        for(int h8=0;h8<2;h8++){
            int c0 = hn*16 + h8*8 + q*2;
            u[h8][0] = B1S[c0]; u[h8][1] = B1S[c0+1];
            u[h8][2] = B1S[c0]; u[h8][3] = B1S[c0+1];
        }
        #pragma unroll
        for(int k16=0;k16<4;k16++){
            uint32_t a2h[4];
            {
                int row = hm*16 + lrow;
                uint32_t off = (uint32_t)row*(DA_ST*2) + (uint32_t)(k16*32 + lhalf*16);
                ldsm4(a2h, sb + DS_A + off);
            }
            uint32_t dh[4];
            {
                int k = k16*16 + lrow;
                uint32_t off = (uint32_t)k*(DD_ST*2) + (uint32_t)(hn*32 + lhalf*16);
                ldsm4t(dh, sb + DS_D1 + off);
            }
            #pragma unroll
            for(int h8=0;h8<2;h8++){
                mma16816h(u[h8], a2h, dh[2*h8], dh[2*h8+1]);
            }
        }
        float pr = 0.f, pr8 = 0.f;
        #pragma unroll
        for(int h8=0;h8<2;h8++){
            int c0 = hn*16 + h8*8 + q*2;
            pr  += fmaxf(u[h8][0],0.f)*D2S[c0] + fmaxf(u[h8][1],0.f)*D2S[c0+1];
            pr8 += fmaxf(u[h8][2],0.f)*D2S[c0] + fmaxf(u[h8][3],0.f)*D2S[c0+1];
        }
        int hr = hm*16 + rql;
        RED[hr*8 + hn*4 + q]     = pr;
        RED[(hr+8)*8 + hn*4 + q] = pr8;
        __syncthreads();
        if(tid < 64){
            float ssum = bd2v;
            #pragma unroll
            for(int e=0;e<8;e++) ssum += RED[tid*8 + e];
            out[ZOUT + (size_t)(r0 + tid)*Sq + s] = ssum;
        }
    }
}

// ------------------------------------------------------------------
extern "C" void kernel_launch(void* const* d_in, const int* in_sizes, int n_in,
                              void* d_out, int out_size)
{
    const float* X    = (const float*)d_in[0];
    const float* adj  = (const float*)d_in[1];
    const float* se   = (const float*)d_in[2];
    const float* W1   = (const float*)d_in[3];
    const float* b1   = (const float*)d_in[4];
    const float* W2   = (const float*)d_in[5];
    const float* b2   = (const float*)d_in[6];
    const float* W_ih = (const float*)d_in[7];
    const float* W_hh = (const float*)d_in[8];
    const float* b_ih = (const float*)d_in[9];
    const float* b_hh = (const float*)d_in[10];
    const float* D1   = (const float*)d_in[11];
    const float* bd1  = (const float*)d_in[12];
    const float* D2   = (const float*)d_in[13];
    const float* bd2  = (const float*)d_in[14];
    float* out = (float*)d_out;

    const int smem_mma = 4*MSTAGE;                                   // 65536
    cudaFuncSetAttribute(k_mma,       cudaFuncAttributeMaxDynamicSharedMemorySize, smem_mma);
    cudaFuncSetAttribute(k_gates_mma, cudaFuncAttributeMaxDynamicSharedMemorySize, GSM_TOT);
    cudaFuncSetAttribute(k_dec_mma,   cudaFuncAttributeMaxDynamicSharedMemorySize, DS_TOT);

    // launch order: k_mma is the 4th launch -> captured by ncu
    k_prep_adj<<<(int)((Nq*(size_t)Nq)/256), 256>>>(adj);
    k_prep_w<<<144, 256>>>(W1, W2, W_ih, W_hh, b_ih, b_hh, D1);
    k_prep_bh<<<NH/256 + (32*4096)/256, 256>>>(se, X);
    for(int t=0; t<Sq; t++){
        k_mma<<<dim3(Nq/128, 6), 256, smem_mma>>>();
        k_gates_mma<<<dim3(Nq/128, Bq, 2), 256, GSM_TOT>>>(b1, b2);
        int cgrid = CELL_BLOCKS + (t+1 < Sq ? (32*4096)/256 : 0);
        k_cell_catx<<<cgrid, 256>>>(se, X, out, t);
    }
    k_dec_mma<<<(Bq*Nq)/64, 256, DS_TOT>>>(bd1, D2, bd2, out);
}

// round 15
// speedup vs baseline: 1.1849x; 1.1849x over previous
#include <cuda_runtime.h>
#include <cuda_bf16.h>
#include <cuda_fp16.h>
#include <math.h>
#include <stdint.h>

#define Bq 8
#define Sq 12
#define Nq 4096
#define Fq 4
#define Hq 64
#define CHW 68                    // F + H
#define NCOL 544                  // logical diffusion cols (b*68+f)
#define AST 1024                  // g_a row stride (fp16): b*128+f, pads zero
#define NPAD 576                  // padded B columns
#define NH  (Nq*Hq)               // 262144
#define N3H (Nq*3*Hq)             // 786432
#define ZOUT ((size_t)Bq*NH)      // offset of recon in output
#define ASCALE 2048.0f
#define AINV   (1.0f/2048.0f)

// -------- persistent scratch (device globals; no allocation) --------
__device__ float g_h[Bq*NH];                        // h_last only (written at t=11)
__device__ __align__(16) __half g_a[(size_t)Nq*AST]; // diffusion out fp16 [m][b*128+f]
__device__ __align__(16) __half g_gate[Bq*N3H];     // sigmoid(gc1) torch-flat, fp16
__device__ __align__(16) __half g_tconv[Bq*NH];     // tanh(gc2), fp16
__device__ __align__(16) __half g_ah[(size_t)Nq*Nq];           // adj*2^11 (fp16)
__device__ __align__(16) __half g_bh[(size_t)Nq*NPAD];         // catT fp16 [k][col]
__device__ __align__(16) __half g_w[80*256];                   // W1|W2 fp16 [k][ch]
// decoder fp16 weights (column-permuted: col = hc*4 + gate)
__device__ __align__(16) __half g_dwih[64*256];
__device__ __align__(16) __half g_dwhh[64*256];
__device__ __align__(16) __half g_d1[64*32];
__device__ float g_dbb[256];                        // permuted b_ih+b_hh

__device__ __forceinline__ float sigf(float x){ return 1.f/(1.f+expf(-x)); }

// ---- warp MMA helpers ----
__device__ __forceinline__ uint32_t smem_u32(const void* p) {
    uint32_t a;
    asm("{ .reg .u64 t; cvta.to.shared.u64 t, %1; cvt.u32.u64 %0, t; }"
        : "=r"(a) : "l"(p));
    return a;
}
__device__ __forceinline__ void cpasync16(uint32_t dst, const void* src){
    asm volatile("cp.async.cg.shared.global [%0], [%1], 16;"
                 :: "r"(dst), "l"(src) : "memory");
}
__device__ __forceinline__ void ldsm4(uint32_t r[4], uint32_t addr){
    asm volatile("ldmatrix.sync.aligned.m8n8.x4.shared.b16 {%0,%1,%2,%3}, [%4];"
                 : "=r"(r[0]), "=r"(r[1]), "=r"(r[2]), "=r"(r[3]) : "r"(addr));
}
__device__ __forceinline__ void ldsm4t(uint32_t r[4], uint32_t addr){
    asm volatile("ldmatrix.sync.aligned.m8n8.x4.trans.shared.b16 {%0,%1,%2,%3}, [%4];"
                 : "=r"(r[0]), "=r"(r[1]), "=r"(r[2]), "=r"(r[3]) : "r"(addr));
}
// fp16 MMA
__device__ __forceinline__ void mma16816h(float d[4], const uint32_t a[4],
                                          uint32_t b0, uint32_t b1){
    asm volatile(
        "mma.sync.aligned.m16n8k16.row.col.f32.f16.f16.f32 "
        "{%0,%1,%2,%3}, {%4,%5,%6,%7}, {%8,%9}, {%0,%1,%2,%3};"
        : "+f"(d[0]), "+f"(d[1]), "+f"(d[2]), "+f"(d[3])
        : "r"(a[0]), "r"(a[1]), "r"(a[2]), "r"(a[3]), "r"(b0), "r"(b1));
}

// ===================== one-time prep (3 kernels; k_mma is launch #4) =====================
__global__ void k_prep_adj(const float* __restrict__ adj){
    size_t i = (size_t)blockIdx.x*256 + threadIdx.x;   // Nq*Nq exactly
    g_ah[i] = __float2half_rn(adj[i] * ASCALE);
}

__global__ void k_prep_w(const float* __restrict__ W1, const float* __restrict__ W2,
                         const float* __restrict__ W_ih, const float* __restrict__ W_hh,
                         const float* __restrict__ b_ih, const float* __restrict__ b_hh,
                         const float* __restrict__ D1){
    if(blockIdx.x < 80){
        int idx = blockIdx.x*256 + threadIdx.x;
        int f = idx >> 8, ch = idx & 255;
        float v = 0.f;
        if(f < 68) v = (ch < 192) ? W1[f*192 + ch] : W2[f*64 + ch - 192];
        g_w[idx] = __float2half_rn(v);
    } else {
        int idx = (blockIdx.x - 80)*256 + threadIdx.x;  // 64*256
        int k = idx >> 8, c = idx & 255;
        int hc = c >> 2, gate = c & 3;
        g_dwih[idx] = __float2half_rn(W_ih[(gate*64 + hc)*64 + k]);
        g_dwhh[idx] = __float2half_rn(W_hh[(gate*64 + hc)*64 + k]);
        if(idx < 64*32) g_d1[idx] = __float2half_rn(D1[idx]);
        if(idx < 256){
            int g2 = idx & 3, h2 = idx >> 2;
            g_dbb[idx] = b_ih[g2*64 + h2] + b_hh[g2*64 + h2];
        }
    }
}

__global__ void k_prep_bh(const float* __restrict__ se, const float* __restrict__ X){
    if(blockIdx.x < NH/256){
        int j = blockIdx.x*256 + threadIdx.x;   // NH exactly
        int n = j >> 6, hc = j & 63;
        __half hv = __float2half_rn(se[j]);
        #pragma unroll
        for(int b=0;b<Bq;b++)
            g_bh[(size_t)n*NPAD + b*CHW + 4 + hc] = hv;
    } else {
        int i = (blockIdx.x - NH/256)*256 + threadIdx.x;   // 32*4096 exactly
        int b = i >> 14, f = (i >> 12) & 3, k = i & 4095;
        float v = X[(size_t)(b*Sq*Nq + k)*Fq + f];  // t = 0
        g_bh[(size_t)k*NPAD + b*CHW + f] = __float2half_rn(v);
    }
}

// ===================== HMMA GEMM (encoder diffusion, fp16, BK=64) =====================
// BM=128, BN=64, BK=64, 4-stage cp.async, 2 CTAs/SM, 256 thr, warp 4m x 2n.
#define MSTAGE 24576
#define MA_OFF 0
#define MB_OFF 16384

__device__ __forceinline__ void mma_load_stage(uint32_t dbase, int s, int kt,
                                               int m0, int n0, int tid){
    const uint32_t sb = dbase + (uint32_t)s*MSTAGE;
    const int k0 = kt*64;
    // A: 128 rows x 8 chunks(16B) = 1024
    #pragma unroll
    for(int it=0; it<4; it++){
        int i = tid + it*256;
        int row = i >> 3, c = i & 7;
        const __half* src = g_ah + ((size_t)(m0+row) << 12) + k0 + c*8;
        uint32_t dst = sb + MA_OFF
            + (uint32_t)row*128 + (uint32_t)((c ^ (row&7))<<4);
        cpasync16(dst, src);
    }
    // B: 64 k-rows x 8 chunks = 512
    #pragma unroll
    for(int it=0; it<2; it++){
        int i = tid + it*256;
        int row = i >> 3, c = i & 7;
        const __half* src = g_bh + (size_t)(k0+row)*NPAD + n0 + c*8;
        uint32_t dst = sb + MB_OFF
            + (uint32_t)row*128 + (uint32_t)((c ^ (row&7))<<4);
        cpasync16(dst, src);
    }
}

__global__ __launch_bounds__(256,2) void k_mma(){
    extern __shared__ char dyn[];
    const uint32_t dbase = smem_u32(dyn);
    const int tid = threadIdx.x;
    const int lane = tid & 31, wid = tid >> 5;
    const int warp_m = wid & 3, warp_n = wid >> 2;
    const int m0 = blockIdx.x * 128;
    const int n0 = blockIdx.y * 64;
    const int lrow = lane & 15, lhalf = lane >> 4;

    float acc[2][4][4];
    #pragma unroll
    for(int mt=0;mt<2;mt++)
        #pragma unroll
        for(int nt=0;nt<4;nt++)
            #pragma unroll
            for(int q=0;q<4;q++) acc[mt][nt][q] = 0.f;

    mma_load_stage(dbase, 0, 0, m0, n0, tid);
    asm volatile("cp.async.commit_group;" ::: "memory");
    mma_load_stage(dbase, 1, 1, m0, n0, tid);
    asm volatile("cp.async.commit_group;" ::: "memory");
    mma_load_stage(dbase, 2, 2, m0, n0, tid);
    asm volatile("cp.async.commit_group;" ::: "memory");

    for(int kt=0; kt<64; kt++){
        if(kt < 62)      { asm volatile("cp.async.wait_group 2;" ::: "memory"); }
        else if(kt == 62){ asm volatile("cp.async.wait_group 1;" ::: "memory"); }
        else             { asm volatile("cp.async.wait_group 0;" ::: "memory"); }
        __syncthreads();

        if(kt + 3 < 64){
            mma_load_stage(dbase, (kt+3)&3, kt+3, m0, n0, tid);
            asm volatile("cp.async.commit_group;" ::: "memory");
        }

        const uint32_t sb = dbase + (uint32_t)(kt&3)*MSTAGE;
        #pragma unroll
        for(int k16=0; k16<4; k16++){
            uint32_t ah[2][4];
            #pragma unroll
            for(int mt=0; mt<2; mt++){
                int row = warp_m*32 + mt*16 + lrow;
                int c = k16*2 + lhalf;
                uint32_t off = (uint32_t)row*128 + (uint32_t)((c ^ (row&7))<<4);
                ldsm4(ah[mt], sb + MA_OFF + off);
            }
            uint32_t bh[2][4];
            #pragma unroll
            for(int nt16=0; nt16<2; nt16++){
                int k = k16*16 + lrow;
                int c = warp_n*4 + nt16*2 + lhalf;
                uint32_t off = (uint32_t)k*128 + (uint32_t)((c ^ (k&7))<<4);
                ldsm4t(bh[nt16], sb + MB_OFF + off);
            }
            #pragma unroll
            for(int mt=0; mt<2; mt++)
                #pragma unroll
                for(int nt16=0; nt16<2; nt16++)
                    #pragma unroll
                    for(int h8=0; h8<2; h8++){
                        mma16816h(acc[mt][nt16*2 + h8], ah[mt],
                                  bh[nt16][2*h8], bh[nt16][2*h8+1]);
                    }
        }
    }

    #pragma unroll
    for(int mt=0; mt<2; mt++){
        #pragma unroll
        for(int nt=0; nt<4; nt++){
            int col = n0 + warp_n*32 + nt*8 + (lane&3)*2;
            if(col < NCOL){
                int bb = col / 68, ff = col - bb*68;
                int colA = bb*128 + ff;                 // packed g_a layout
                int r0 = m0 + warp_m*32 + mt*16 + (lane>>2);
                __half2 h0 = __halves2half2(__float2half_rn(acc[mt][nt][0]*AINV),
                                            __float2half_rn(acc[mt][nt][1]*AINV));
                __half2 h1 = __halves2half2(__float2half_rn(acc[mt][nt][2]*AINV),
                                            __float2half_rn(acc[mt][nt][3]*AINV));
                *(__half2*)(g_a + (size_t)r0*AST + colA)     = h0;
                *(__half2*)(g_a + (size_t)(r0+8)*AST + colA) = h1;
            }
        }
    }
}

// ===================== gates GEMM + activations (fp16) =====================
#define GA_B 272
#define GW_B 272
#define GSM_A 0
#define GSM_W (128*GA_B)                    // 34816
#define GSM_BC (GSM_W + 80*GW_B)            // 56576
#define GSM_TOT (GSM_BC + 128*4)            // 57088

__global__ __launch_bounds__(256,2) void k_gates_mma(
        const float* __restrict__ b1, const float* __restrict__ b2){
    extern __shared__ char smg[];
    const uint32_t sb = smem_u32(smg);
    float* bc = (float*)(smg + GSM_BC);
    const int tid = threadIdx.x, lane = tid & 31, wid = tid >> 5;
    const int warp_m = wid & 3, warp_n = wid >> 2;
    const int m0 = blockIdx.x * 128;
    const int b  = blockIdx.y;
    const int z  = blockIdx.z;
    const int lrow = lane & 15, lhalf = lane >> 4;

    #pragma unroll
    for(int it=0; it<8; it++){
        int i = tid + it*256;
        int row = i >> 4, c = i & 15;
        const __half* src = g_a + (size_t)(m0+row)*AST + b*128 + c*8;
        cpasync16(sb + GSM_A + (uint32_t)row*GA_B + (uint32_t)c*16, src);
    }
    #pragma unroll
    for(int it=0; it<5; it++){
        int i = tid + it*256;
        int f = i >> 4, c = i & 15;
        const __half* src = g_w + f*256 + z*128 + c*8;
        cpasync16(sb + GSM_W + (uint32_t)f*GW_B + (uint32_t)c*16, src);
    }
    asm volatile("cp.async.commit_group;" ::: "memory");
    if(tid < 128){
        int ch = z*128 + tid;
        bc[tid] = (ch < 192) ? b1[ch] : b2[ch - 192];
    }
    asm volatile("cp.async.wait_group 0;" ::: "memory");
    __syncthreads();

    float acc[2][8][4];
    #pragma unroll
    for(int mt=0;mt<2;mt++)
        #pragma unroll
        for(int nt=0;nt<8;nt++)
            #pragma unroll
            for(int q=0;q<4;q++) acc[mt][nt][q] = 0.f;

    #pragma unroll
    for(int k16=0; k16<5; k16++){
        uint32_t ah[2][4];
        #pragma unroll
        for(int mt=0; mt<2; mt++){
            int row = warp_m*32 + mt*16 + lrow;
            uint32_t off = (uint32_t)row*GA_B + (uint32_t)(k16*32 + lhalf*16);
            ldsm4(ah[mt], sb + GSM_A + off);
        }
        uint32_t bh[4][4];
        #pragma unroll
        for(int nt16=0; nt16<4; nt16++){
            int k = k16*16 + lrow;
            uint32_t off = (uint32_t)k*GW_B
                + (uint32_t)(warp_n*128 + nt16*32 + lhalf*16);
            ldsm4t(bh[nt16], sb + GSM_W + off);
        }
        #pragma unroll
        for(int mt=0; mt<2; mt++)
            #pragma unroll
            for(int nt16=0; nt16<4; nt16++)
                #pragma unroll
                for(int h8=0; h8<2; h8++){
                    mma16816h(acc[mt][nt16*2 + h8], ah[mt],
                              bh[nt16][2*h8], bh[nt16][2*h8+1]);
                }
    }

    #pragma unroll
    for(int mt=0; mt<2; mt++){
        #pragma unroll
        for(int nt=0; nt<8; nt++){
            int col = warp_n*64 + nt*8 + (lane&3)*2;
            int ch  = z*128 + col;
            float bb0 = bc[col], bb1 = bc[col+1];
            int r0 = m0 + warp_m*32 + mt*16 + (lane>>2);
            #pragma unroll
            for(int hf=0; hf<2; hf++){
                int node = r0 + 8*hf;
                float v0 = acc[mt][nt][2*hf]   + bb0;
                float v1 = acc[mt][nt][2*hf+1] + bb1;
                if(ch < 192){
                    __half2 o = __halves2half2(__float2half_rn(sigf(v0)),
                                               __float2half_rn(sigf(v1)));
                    *(__half2*)(g_gate + (size_t)b*N3H + (size_t)node*192 + ch) = o;
                }else{
                    __half2 o = __halves2half2(__float2half_rn(tanhf(v0)),
                                               __float2half_rn(tanhf(v1)));
                    *(__half2*)(g_tconv + (size_t)b*NH + (size_t)node*64 + (ch-192)) = o;
                }
            }
        }
    }
}

// -------- fused: LSTM cell (2 elems/thread) + catT X cols for t+1; z-out at t=11 --------
#define CELL_BLOCKS ((Bq*NH)/512)
__global__ void k_cell_catx(const float* __restrict__ se, const float* __restrict__ X,
                            float* __restrict__ out, int t){
    if(blockIdx.x < CELL_BLOCKS){
        int idx = (blockIdx.x*256 + threadIdx.x)*2;   // even, covers Bq*NH
        int b = idx >> 18;
        int j = idx & (NH-1);
        const __half* gg = g_gate + (size_t)b*N3H;
        __half2 f2 = *(const __half2*)(gg + j);
        __half2 i2 = *(const __half2*)(gg + NH + j);
        __half2 o2 = *(const __half2*)(gg + 2*NH + j);
        __half2 t2 = *(const __half2*)(g_tconv + (size_t)b*NH + j);
        float2 se2 = *(const float2*)(se + j);
        float c0 = __low2float(f2)*se2.x  + __low2float(i2)*__low2float(t2);
        float c1 = __high2float(f2)*se2.y + __high2float(i2)*__high2float(t2);
        float h0 = __low2float(o2)  * tanhf(c0);
        float h1 = __high2float(o2) * tanhf(c1);
        int n = j >> 6, hc = j & 63;
        *(__half2*)(g_bh + (size_t)n*NPAD + b*CHW + 4 + hc) =
            __halves2half2(__float2half_rn(h0), __float2half_rn(h1));
        if(t == Sq-1){
            float2 hv; hv.x = h0; hv.y = h1;
            *(float2*)(g_h + idx) = hv;
            *(float2*)(out + idx) = hv;
        }
    } else {
        int i = (blockIdx.x - CELL_BLOCKS)*256 + threadIdx.x;  // 32*4096
        int b = i >> 14, f = (i >> 12) & 3, k = i & 4095;
        float v = X[(size_t)((b*Sq + t + 1)*Nq + k)*Fq + f];
        g_bh[(size_t)k*NPAD + b*CHW + f] = __float2half_rn(v);
    }
}

// ===================== MMA decoder (fp16, XG fp16, occ-2) =====================
#define DW_ST 264
#define DA_ST 72
#define DXH   264
#define DD_ST 40
#define DS_W  0
#define DS_A  (DS_W + 64*DW_ST*2)           // 33792
#define DS_XG (DS_A + 64*DA_ST*2)           // 43008
#define DS_D1 (DS_XG + 64*DXH*2)            // 76800
#define DS_RED (DS_D1 + 64*DD_ST*2)         // 81920
#define DS_BB  (DS_RED + 64*8*4)            // 83968
#define DS_B1  (DS_BB + 256*4)              // 84992
#define DS_D2  (DS_B1 + 32*4)               // 85120
#define DS_TOT (DS_D2 + 32*4)               // 85248

__device__ __forceinline__ void dec_gemm_k64(float acc[2][8][4], uint32_t sb,
        int wm, int wn, int lrow, int lhalf){
    #pragma unroll
    for(int k16=0;k16<4;k16++){
        uint32_t ah[2][4];
        #pragma unroll
        for(int mt=0;mt<2;mt++){
            int row = wm*32 + mt*16 + lrow;
            uint32_t off = (uint32_t)row*(DA_ST*2) + (uint32_t)(k16*32 + lhalf*16);
            ldsm4(ah[mt], sb + DS_A + off);
        }
        uint32_t bh[4][4];
        #pragma unroll
        for(int nt16=0;nt16<4;nt16++){
            int k = k16*16 + lrow;
            uint32_t off = (uint32_t)k*(DW_ST*2)
                + (uint32_t)(wn*128 + nt16*32 + lhalf*16);
            ldsm4t(bh[nt16], sb + DS_W + off);
        }
        #pragma unroll
        for(int mt=0;mt<2;mt++)
            #pragma unroll
            for(int nt16=0;nt16<4;nt16++)
                #pragma unroll
                for(int h8=0;h8<2;h8++){
                    mma16816h(acc[mt][nt16*2 + h8], ah[mt],
                              bh[nt16][2*h8], bh[nt16][2*h8+1]);
                }
    }
}

__global__ __launch_bounds__(256,2) void k_dec_mma(
        const float* __restrict__ bd1, const float* __restrict__ D2,
        const float* __restrict__ bd2, float* __restrict__ out)
{
    extern __shared__ char smd[];
    const uint32_t sb = smem_u32(smd);
    __half* WS = (__half*)(smd + DS_W);
    __half* AS = (__half*)(smd + DS_A);
    __half* XG = (__half*)(smd + DS_XG);
    __half* D1S16 = (__half*)(smd + DS_D1);
    float* RED = (float*)(smd + DS_RED);
    float* BB  = (float*)(smd + DS_BB);
    float* B1S = (float*)(smd + DS_B1);
    float* D2S = (float*)(smd + DS_D2);
    const int tid = threadIdx.x, lane = tid & 31, wid = tid >> 5;
    const int r0 = blockIdx.x * 64;
    const int lrow = lane & 15, lhalf = lane >> 4;
    const int q = lane & 3, rql = lane >> 2;
    const int wm = wid & 1, wn = wid >> 1;
    const int hm = wid >> 1, hn = wid & 1;

    for(int idx=tid; idx<64*64; idx+=256){
        int row = idx >> 6, k = idx & 63;
        AS[row*DA_ST + k] = __float2half_rn(g_h[(size_t)(r0+row)*64 + k]);
    }
    for(int idx=tid; idx<64*256; idx+=256){
        int k = idx >> 8, c = idx & 255;
        WS[k*DW_ST + c] = g_dwih[idx];
    }
    {
        const __half zh = __float2half_rn(0.f);
        for(int idx=tid; idx<64*DD_ST; idx+=256){
            int k = idx / DD_ST, c = idx - k*DD_ST;
            D1S16[idx] = (c < 32) ? g_d1[k*32 + c] : zh;
        }
    }
    if(tid < 256) BB[tid] = g_dbb[tid];
    if(tid < 32){ B1S[tid] = bd1[tid]; D2S[tid] = D2[tid]; }
    __syncthreads();

    {
        float acc[2][8][4];
        #pragma unroll
        for(int mt=0;mt<2;mt++)
            #pragma unroll
            for(int nt=0;nt<8;nt++){
                int c0 = wn*64 + nt*8 + q*2;
                acc[mt][nt][0] = BB[c0];   acc[mt][nt][1] = BB[c0+1];
                acc[mt][nt][2] = BB[c0];   acc[mt][nt][3] = BB[c0+1];
            }
        dec_gemm_k64(acc, sb, wm, wn, lrow, lhalf);
        #pragma unroll
        for(int mt=0;mt<2;mt++)
            #pragma unroll
            for(int nt=0;nt<8;nt++){
                int r = wm*32 + mt*16 + rql;
                int c0 = wn*64 + nt*8 + q*2;
                *(__half2*)(XG + r*DXH + c0) =
                    __halves2half2(__float2half_rn(acc[mt][nt][0]),
                                   __float2half_rn(acc[mt][nt][1]));
                *(__half2*)(XG + (r+8)*DXH + c0) =
                    __halves2half2(__float2half_rn(acc[mt][nt][2]),
                                   __float2half_rn(acc[mt][nt][3]));
            }
    }
    __syncthreads();
    for(int idx=tid; idx<64*256; idx+=256){
        int k = idx >> 8, c = idx & 255;
        WS[k*DW_ST + c] = g_dwhh[idx];
    }
    __syncthreads();

    float cst[2][8];
    #pragma unroll
    for(int mt=0;mt<2;mt++)
        #pragma unroll
        for(int nt=0;nt<8;nt++) cst[mt][nt] = 0.f;
    const float bd2v = bd2[0];

    for(int s=0; s<Sq; s++){
        float acc[2][8][4];
        #pragma unroll
        for(int mt=0;mt<2;mt++)
            #pragma unroll
            for(int nt=0;nt<8;nt++){
                int r = wm*32 + mt*16 + rql;
                int c0 = wn*64 + nt*8 + q*2;
                float2 lo = __half22float2(*(const __half2*)(XG + r*DXH + c0));
                float2 hi = __half22float2(*(const __half2*)(XG + (r+8)*DXH + c0));
                acc[mt][nt][0] = lo.x; acc[mt][nt][1] = lo.y;
                acc[mt][nt][2] = hi.x; acc[mt][nt][3] = hi.y;
            }
        if(s > 0) dec_gemm_k64(acc, sb, wm, wn, lrow, lhalf);
        __syncthreads();

        #pragma unroll
        for(int mt=0;mt<2;mt++){
            #pragma unroll
            for(int nt=0;nt<8;nt++){
                float d0 = acc[mt][nt][0], d1 = acc[mt][nt][1];
                float d2 = acc[mt][nt][2], d3 = acc[mt][nt][3];
                float e0 = __shfl_xor_sync(0xffffffffu, d0, 1);
                float e1 = __shfl_xor_sync(0xffffffffu, d1, 1);
                float e2 = __shfl_xor_sync(0xffffffffu, d2, 1);
                float e3 = __shfl_xor_sync(0xffffffffu, d3, 1);
                float iv, fv, gv, ov;
                if((lane & 1) == 0){ iv = d0; fv = d1; gv = e0; ov = e1; }
                else               { iv = e2; fv = e3; gv = d2; ov = d3; }
                float cc = sigf(fv)*cst[mt][nt] + sigf(iv)*tanhf(gv);
                cst[mt][nt] = cc;
                float hh = sigf(ov)*tanhf(cc);
                int row = wm*32 + mt*16 + rql + ((lane & 1) << 3);
                int hc  = wn*16 + nt*2 + (q >> 1);
                AS[row*DA_ST + hc] = __float2half_rn(hh);
            }
        }
        __syncthreads();

        float u[2][4];
        #pragma unroll
        for(int h8=0;h8<2;h8++){
            int c0 = hn*16 + h8*8 + q*2;
            u[h8][0] = B1S[c0]; u[h8][1] = B1S[c0+1];
            u[h8][2] = B1S[c0]; u[h8][3] = B1S[c0+1];
        }
        #pragma unroll
        for(int k16=0;k16<4;k16++){
            uint32_t a2h[4];
            {
                int row = hm*16 + lrow;
                uint32_t off = (uint32_t)row*(DA_ST*2) + (uint32_t)(k16*32 + lhalf*16);
                ldsm4(a2h, sb + DS_A + off);
            }
            uint32_t dh[4];
            {
                int k = k16*16 + lrow;
                uint32_t off = (uint32_t)k*(DD_ST*2) + (uint32_t)(hn*32 + lhalf*16);
                ldsm4t(dh, sb + DS_D1 + off);
            }
            #pragma unroll
            for(int h8=0;h8<2;h8++){
                mma16816h(u[h8], a2h, dh[2*h8], dh[2*h8+1]);
            }
        }
        float pr = 0.f, pr8 = 0.f;
        #pragma unroll
        for(int h8=0;h8<2;h8++){
            int c0 = hn*16 + h8*8 + q*2;
            pr  += fmaxf(u[h8][0],0.f)*D2S[c0] + fmaxf(u[h8][1],0.f)*D2S[c0+1];
            pr8 += fmaxf(u[h8][2],0.f)*D2S[c0] + fmaxf(u[h8][3],0.f)*D2S[c0+1];
        }
        int hr = hm*16 + rql;
        RED[hr*8 + hn*4 + q]     = pr;
        RED[(hr+8)*8 + hn*4 + q] = pr8;
        __syncthreads();
        if(tid < 64){
            float ssum = bd2v;
            #pragma unroll
            for(int e=0;e<8;e++) ssum += RED[tid*8 + e];
            out[ZOUT + (size_t)(r0 + tid)*Sq + s] = ssum;
        }
    }
}

// ------------------------------------------------------------------
extern "C" void kernel_launch(void* const* d_in, const int* in_sizes, int n_in,
                              void* d_out, int out_size)
{
    const float* X    = (const float*)d_in[0];
    const float* adj  = (const float*)d_in[1];
    const float* se   = (const float*)d_in[2];
    const float* W1   = (const float*)d_in[3];
    const float* b1   = (const float*)d_in[4];
    const float* W2   = (const float*)d_in[5];
    const float* b2   = (const float*)d_in[6];
    const float* W_ih = (const float*)d_in[7];
    const float* W_hh = (const float*)d_in[8];
    const float* b_ih = (const float*)d_in[9];
    const float* b_hh = (const float*)d_in[10];
    const float* D1   = (const float*)d_in[11];
    const float* bd1  = (const float*)d_in[12];
    const float* D2   = (const float*)d_in[13];
    const float* bd2  = (const float*)d_in[14];
    float* out = (float*)d_out;

    const int smem_mma = 4*MSTAGE;                                   // 98304
    cudaFuncSetAttribute(k_mma,       cudaFuncAttributeMaxDynamicSharedMemorySize, smem_mma);
    cudaFuncSetAttribute(k_gates_mma, cudaFuncAttributeMaxDynamicSharedMemorySize, GSM_TOT);
    cudaFuncSetAttribute(k_dec_mma,   cudaFuncAttributeMaxDynamicSharedMemorySize, DS_TOT);

    // launch order: k_mma is the 4th launch -> captured by ncu
    k_prep_adj<<<(int)((Nq*(size_t)Nq)/256), 256>>>(adj);
    k_prep_w<<<144, 256>>>(W1, W2, W_ih, W_hh, b_ih, b_hh, D1);
    k_prep_bh<<<NH/256 + (32*4096)/256, 256>>>(se, X);
    for(int t=0; t<Sq; t++){
        k_mma<<<dim3(Nq/128, 9), 256, smem_mma>>>();
        k_gates_mma<<<dim3(Nq/128, Bq, 2), 256, GSM_TOT>>>(b1, b2);
        int cgrid = CELL_BLOCKS + (t+1 < Sq ? (32*4096)/256 : 0);
        k_cell_catx<<<cgrid, 256>>>(se, X, out, t);
    }
    k_dec_mma<<<(Bq*Nq)/64, 256, DS_TOT>>>(bd1, D2, bd2, out);
}

// round 16
// speedup vs baseline: 1.2361x; 1.0432x over previous
#include <cuda_runtime.h>
#include <cuda_bf16.h>
#include <cuda_fp16.h>
#include <math.h>
#include <stdint.h>

#define Bq 8
#define Sq 12
#define Nq 4096
#define Fq 4
#define Hq 64
#define CHW 68                    // F + H
#define NCOL 544                  // logical diffusion cols (b*68+f)
#define AST 1024                  // g_a row stride (fp16): b*128+f, pads zero
#define NPAD 576                  // padded B columns
#define NH  (Nq*Hq)               // 262144
#define N3H (Nq*3*Hq)             // 786432
#define ZOUT ((size_t)Bq*NH)      // offset of recon in output
#define ASCALE 2048.0f
#define AINV   (1.0f/2048.0f)

// -------- persistent scratch (device globals; no allocation) --------
__device__ float g_h[Bq*NH];                        // h_last only (written at t=11)
__device__ __align__(16) __half g_a[(size_t)Nq*AST]; // diffusion out fp16 [m][b*128+f]
__device__ __align__(16) __half g_gate[Bq*N3H];     // sigmoid(gc1) torch-flat, fp16
__device__ __align__(16) __half g_tconv[Bq*NH];     // tanh(gc2), fp16
__device__ __align__(16) __half g_ah[(size_t)Nq*Nq];           // adj*2^11 (fp16)
__device__ __align__(16) __half g_bh[(size_t)Nq*NPAD];         // catT fp16 [k][col]
__device__ __align__(16) __half g_w[80*256];                   // W1|W2 fp16 [k][ch]
// decoder fp16 weights (column-permuted: col = hc*4 + gate)
__device__ __align__(16) __half g_dwih[64*256];
__device__ __align__(16) __half g_dwhh[64*256];
__device__ __align__(16) __half g_d1[64*32];
__device__ float g_dbb[256];                        // permuted b_ih+b_hh

__device__ __forceinline__ float sigf(float x){ return 1.f/(1.f+expf(-x)); }

// ---- warp MMA helpers ----
__device__ __forceinline__ uint32_t smem_u32(const void* p) {
    uint32_t a;
    asm("{ .reg .u64 t; cvta.to.shared.u64 t, %1; cvt.u32.u64 %0, t; }"
        : "=r"(a) : "l"(p));
    return a;
}
__device__ __forceinline__ void cpasync16(uint32_t dst, const void* src){
    asm volatile("cp.async.cg.shared.global [%0], [%1], 16;"
                 :: "r"(dst), "l"(src) : "memory");
}
__device__ __forceinline__ void ldsm4(uint32_t r[4], uint32_t addr){
    asm volatile("ldmatrix.sync.aligned.m8n8.x4.shared.b16 {%0,%1,%2,%3}, [%4];"
                 : "=r"(r[0]), "=r"(r[1]), "=r"(r[2]), "=r"(r[3]) : "r"(addr));
}
__device__ __forceinline__ void ldsm4t(uint32_t r[4], uint32_t addr){
    asm volatile("ldmatrix.sync.aligned.m8n8.x4.trans.shared.b16 {%0,%1,%2,%3}, [%4];"
                 : "=r"(r[0]), "=r"(r[1]), "=r"(r[2]), "=r"(r[3]) : "r"(addr));
}
// fp16 MMA
__device__ __forceinline__ void mma16816h(float d[4], const uint32_t a[4],
                                          uint32_t b0, uint32_t b1){
    asm volatile(
        "mma.sync.aligned.m16n8k16.row.col.f32.f16.f16.f32 "
        "{%0,%1,%2,%3}, {%4,%5,%6,%7}, {%8,%9}, {%0,%1,%2,%3};"
        : "+f"(d[0]), "+f"(d[1]), "+f"(d[2]), "+f"(d[3])
        : "r"(a[0]), "r"(a[1]), "r"(a[2]), "r"(a[3]), "r"(b0), "r"(b1));
}

// ===================== one-time prep (3 kernels; k_mma is launch #4) =====================
__global__ void k_prep_adj(const float* __restrict__ adj){
    size_t i = (size_t)blockIdx.x*256 + threadIdx.x;   // Nq*Nq exactly
    g_ah[i] = __float2half_rn(adj[i] * ASCALE);
}

__global__ void k_prep_w(const float* __restrict__ W1, const float* __restrict__ W2,
                         const float* __restrict__ W_ih, const float* __restrict__ W_hh,
                         const float* __restrict__ b_ih, const float* __restrict__ b_hh,
                         const float* __restrict__ D1){
    if(blockIdx.x < 80){
        int idx = blockIdx.x*256 + threadIdx.x;
        int f = idx >> 8, ch = idx & 255;
        float v = 0.f;
        if(f < 68) v = (ch < 192) ? W1[f*192 + ch] : W2[f*64 + ch - 192];
        g_w[idx] = __float2half_rn(v);
    } else {
        int idx = (blockIdx.x - 80)*256 + threadIdx.x;  // 64*256
        int k = idx >> 8, c = idx & 255;
        int hc = c >> 2, gate = c & 3;
        g_dwih[idx] = __float2half_rn(W_ih[(gate*64 + hc)*64 + k]);
        g_dwhh[idx] = __float2half_rn(W_hh[(gate*64 + hc)*64 + k]);
        if(idx < 64*32) g_d1[idx] = __float2half_rn(D1[idx]);
        if(idx < 256){
            int g2 = idx & 3, h2 = idx >> 2;
            g_dbb[idx] = b_ih[g2*64 + h2] + b_hh[g2*64 + h2];
        }
    }
}

__global__ void k_prep_bh(const float* __restrict__ se, const float* __restrict__ X){
    if(blockIdx.x < NH/256){
        int j = blockIdx.x*256 + threadIdx.x;   // NH exactly
        int n = j >> 6, hc = j & 63;
        __half hv = __float2half_rn(se[j]);
        #pragma unroll
        for(int b=0;b<Bq;b++)
            g_bh[(size_t)n*NPAD + b*CHW + 4 + hc] = hv;
    } else {
        int i = (blockIdx.x - NH/256)*256 + threadIdx.x;   // 32*4096 exactly
        int b = i >> 14, f = (i >> 12) & 3, k = i & 4095;
        float v = X[(size_t)(b*Sq*Nq + k)*Fq + f];  // t = 0
        g_bh[(size_t)k*NPAD + b*CHW + f] = __float2half_rn(v);
    }
}

// ===================== HMMA GEMM (encoder diffusion, fp16, BK=32 — R13 config) =====
#define MSTAGE 12288
#define MA_OFF 0
#define MB_OFF 8192

__device__ __forceinline__ void mma_load_stage(uint32_t dbase, int s, int kt,
                                               int m0, int n0, int tid){
    const uint32_t sb = dbase + (uint32_t)s*MSTAGE;
    const int k0 = kt*32;
    #pragma unroll
    for(int it=0; it<2; it++){
        int i = tid + it*256;
        int row = i >> 2, c = i & 3;
        const __half* src = g_ah + ((size_t)(m0+row) << 12) + k0 + c*8;
        uint32_t dst = sb + MA_OFF
            + (uint32_t)row*64 + (uint32_t)((c ^ ((row>>1)&3))<<4);
        cpasync16(dst, src);
    }
    {
        int i = tid;
        int row = i >> 3, c = i & 7;
        const __half* src = g_bh + (size_t)(k0+row)*NPAD + n0 + c*8;
        uint32_t dst = sb + MB_OFF
            + (uint32_t)row*128 + (uint32_t)((c ^ (row&7))<<4);
        cpasync16(dst, src);
    }
}

__global__ __launch_bounds__(256,2) void k_mma(){
    extern __shared__ char dyn[];
    const uint32_t dbase = smem_u32(dyn);
    const int tid = threadIdx.x;
    const int lane = tid & 31, wid = tid >> 5;
    const int warp_m = wid & 3, warp_n = wid >> 2;
    const int m0 = blockIdx.x * 128;
    const int n0 = blockIdx.y * 64;
    const int lrow = lane & 15, lhalf = lane >> 4;

    float acc[2][4][4];
    #pragma unroll
    for(int mt=0;mt<2;mt++)
        #pragma unroll
        for(int nt=0;nt<4;nt++)
            #pragma unroll
            for(int q=0;q<4;q++) acc[mt][nt][q] = 0.f;

    mma_load_stage(dbase, 0, 0, m0, n0, tid);
    asm volatile("cp.async.commit_group;" ::: "memory");
    mma_load_stage(dbase, 1, 1, m0, n0, tid);
    asm volatile("cp.async.commit_group;" ::: "memory");
    mma_load_stage(dbase, 2, 2, m0, n0, tid);
    asm volatile("cp.async.commit_group;" ::: "memory");

    for(int kt=0; kt<128; kt++){
        if(kt < 126)      { asm volatile("cp.async.wait_group 2;" ::: "memory"); }
        else if(kt == 126){ asm volatile("cp.async.wait_group 1;" ::: "memory"); }
        else              { asm volatile("cp.async.wait_group 0;" ::: "memory"); }
        __syncthreads();

        if(kt + 3 < 128){
            mma_load_stage(dbase, (kt+3)&3, kt+3, m0, n0, tid);
            asm volatile("cp.async.commit_group;" ::: "memory");
        }

        const uint32_t sb = dbase + (uint32_t)(kt&3)*MSTAGE;
        #pragma unroll
        for(int k16=0; k16<2; k16++){
            uint32_t ah[2][4];
            #pragma unroll
            for(int mt=0; mt<2; mt++){
                int row = warp_m*32 + mt*16 + lrow;
                int c = k16*2 + lhalf;
                uint32_t off = (uint32_t)row*64 + (uint32_t)((c ^ ((row>>1)&3))<<4);
                ldsm4(ah[mt], sb + MA_OFF + off);
            }
            uint32_t bh[2][4];
            #pragma unroll
            for(int nt16=0; nt16<2; nt16++){
                int k = k16*16 + lrow;
                int c = warp_n*4 + nt16*2 + lhalf;
                uint32_t off = (uint32_t)k*128 + (uint32_t)((c ^ (k&7))<<4);
                ldsm4t(bh[nt16], sb + MB_OFF + off);
            }
            #pragma unroll
            for(int mt=0; mt<2; mt++)
                #pragma unroll
                for(int nt16=0; nt16<2; nt16++)
                    #pragma unroll
                    for(int h8=0; h8<2; h8++){
                        mma16816h(acc[mt][nt16*2 + h8], ah[mt],
                                  bh[nt16][2*h8], bh[nt16][2*h8+1]);
                    }
        }
    }

    #pragma unroll
    for(int mt=0; mt<2; mt++){
        #pragma unroll
        for(int nt=0; nt<4; nt++){
            int col = n0 + warp_n*32 + nt*8 + (lane&3)*2;
            if(col < NCOL){
                int bb = col / 68, ff = col - bb*68;
                int colA = bb*128 + ff;                 // packed g_a layout
                int r0 = m0 + warp_m*32 + mt*16 + (lane>>2);
                __half2 h0 = __halves2half2(__float2half_rn(acc[mt][nt][0]*AINV),
                                            __float2half_rn(acc[mt][nt][1]*AINV));
                __half2 h1 = __halves2half2(__float2half_rn(acc[mt][nt][2]*AINV),
                                            __float2half_rn(acc[mt][nt][3]*AINV));
                *(__half2*)(g_a + (size_t)r0*AST + colA)     = h0;
                *(__half2*)(g_a + (size_t)(r0+8)*AST + colA) = h1;
            }
        }
    }
}

// ===================== gates GEMM + activations (fp16, z-merged) =====================
// Per block: 128 nodes x 256 channels (both z halves); a-tile filled once.
#define GA_B 272
#define GW_B 272
#define GSM_A 0
#define GSM_W0 (128*GA_B)                   // 34816
#define GSM_W1 (GSM_W0 + 80*GW_B)           // 56576
#define GSM_BC (GSM_W1 + 80*GW_B)           // 78336
#define GSM_TOT (GSM_BC + 256*4)            // 79360

__global__ __launch_bounds__(256,2) void k_gates_mma(
        const float* __restrict__ b1, const float* __restrict__ b2){
    extern __shared__ char smg[];
    const uint32_t sb = smem_u32(smg);
    float* bc = (float*)(smg + GSM_BC);
    const int tid = threadIdx.x, lane = tid & 31, wid = tid >> 5;
    const int warp_m = wid & 3, warp_n = wid >> 2;
    const int m0 = blockIdx.x * 128;
    const int b  = blockIdx.y;
    const int lrow = lane & 15, lhalf = lane >> 4;

    // a-tile: 128 rows x 16 chunks (16B) — filled ONCE for both z halves
    #pragma unroll
    for(int it=0; it<8; it++){
        int i = tid + it*256;
        int row = i >> 4, c = i & 15;
        const __half* src = g_a + (size_t)(m0+row)*AST + b*128 + c*8;
        cpasync16(sb + GSM_A + (uint32_t)row*GA_B + (uint32_t)c*16, src);
    }
    // W tiles for z=0 and z=1: 2 x 80 rows x 16 chunks
    #pragma unroll
    for(int it=0; it<10; it++){
        int z2 = it / 5;
        int i = tid + (it - z2*5)*256;
        int f = i >> 4, c = i & 15;
        const __half* src = g_w + f*256 + z2*128 + c*8;
        cpasync16(sb + (z2 ? GSM_W1 : GSM_W0)
                  + (uint32_t)f*GW_B + (uint32_t)c*16, src);
    }
    asm volatile("cp.async.commit_group;" ::: "memory");
    {
        int ch = tid;   // 0..255
        bc[ch] = (ch < 192) ? b1[ch] : b2[ch - 192];
    }
    asm volatile("cp.async.wait_group 0;" ::: "memory");
    __syncthreads();

    #pragma unroll
    for(int z = 0; z < 2; z++){
        const uint32_t wbase = sb + (z ? GSM_W1 : GSM_W0);
        float acc[2][8][4];
        #pragma unroll
        for(int mt=0;mt<2;mt++)
            #pragma unroll
            for(int nt=0;nt<8;nt++)
                #pragma unroll
                for(int q=0;q<4;q++) acc[mt][nt][q] = 0.f;

        #pragma unroll
        for(int k16=0; k16<5; k16++){
            uint32_t ah[2][4];
            #pragma unroll
            for(int mt=0; mt<2; mt++){
                int row = warp_m*32 + mt*16 + lrow;
                uint32_t off = (uint32_t)row*GA_B + (uint32_t)(k16*32 + lhalf*16);
                ldsm4(ah[mt], sb + GSM_A + off);
            }
            uint32_t bh[4][4];
            #pragma unroll
            for(int nt16=0; nt16<4; nt16++){
                int k = k16*16 + lrow;
                uint32_t off = (uint32_t)k*GW_B
                    + (uint32_t)(warp_n*128 + nt16*32 + lhalf*16);
                ldsm4t(bh[nt16], wbase + off);
            }
            #pragma unroll
            for(int mt=0; mt<2; mt++)
                #pragma unroll
                for(int nt16=0; nt16<4; nt16++)
                    #pragma unroll
                    for(int h8=0; h8<2; h8++){
                        mma16816h(acc[mt][nt16*2 + h8], ah[mt],
                                  bh[nt16][2*h8], bh[nt16][2*h8+1]);
                    }
        }

        #pragma unroll
        for(int mt=0; mt<2; mt++){
            #pragma unroll
            for(int nt=0; nt<8; nt++){
                int col = warp_n*64 + nt*8 + (lane&3)*2;
                int ch  = z*128 + col;
                float bb0 = bc[ch], bb1 = bc[ch+1];
                int r0 = m0 + warp_m*32 + mt*16 + (lane>>2);
                #pragma unroll
                for(int hf=0; hf<2; hf++){
                    int node = r0 + 8*hf;
                    float v0 = acc[mt][nt][2*hf]   + bb0;
                    float v1 = acc[mt][nt][2*hf+1] + bb1;
                    if(ch < 192){
                        __half2 o = __halves2half2(__float2half_rn(sigf(v0)),
                                                   __float2half_rn(sigf(v1)));
                        *(__half2*)(g_gate + (size_t)b*N3H + (size_t)node*192 + ch) = o;
                    }else{
                        __half2 o = __halves2half2(__float2half_rn(tanhf(v0)),
                                                   __float2half_rn(tanhf(v1)));
                        *(__half2*)(g_tconv + (size_t)b*NH + (size_t)node*64 + (ch-192)) = o;
                    }
                }
            }
        }
    }
}

// -------- fused: LSTM cell (2 elems/thread) + catT X cols for t+1; z-out at t=11 --------
#define CELL_BLOCKS ((Bq*NH)/512)
__global__ void k_cell_catx(const float* __restrict__ se, const float* __restrict__ X,
                            float* __restrict__ out, int t){
    if(blockIdx.x < CELL_BLOCKS){
        int idx = (blockIdx.x*256 + threadIdx.x)*2;   // even, covers Bq*NH
        int b = idx >> 18;
        int j = idx & (NH-1);
        const __half* gg = g_gate + (size_t)b*N3H;
        __half2 f2 = *(const __half2*)(gg + j);
        __half2 i2 = *(const __half2*)(gg + NH + j);
        __half2 o2 = *(const __half2*)(gg + 2*NH + j);
        __half2 t2 = *(const __half2*)(g_tconv + (size_t)b*NH + j);
        float2 se2 = *(const float2*)(se + j);
        float c0 = __low2float(f2)*se2.x  + __low2float(i2)*__low2float(t2);
        float c1 = __high2float(f2)*se2.y + __high2float(i2)*__high2float(t2);
        float h0 = __low2float(o2)  * tanhf(c0);
        float h1 = __high2float(o2) * tanhf(c1);
        int n = j >> 6, hc = j & 63;
        *(__half2*)(g_bh + (size_t)n*NPAD + b*CHW + 4 + hc) =
            __halves2half2(__float2half_rn(h0), __float2half_rn(h1));
        if(t == Sq-1){
            float2 hv; hv.x = h0; hv.y = h1;
            *(float2*)(g_h + idx) = hv;
            *(float2*)(out + idx) = hv;
        }
    } else {
        int i = (blockIdx.x - CELL_BLOCKS)*256 + threadIdx.x;  // 32*4096
        int b = i >> 14, f = (i >> 12) & 3, k = i & 4095;
        float v = X[(size_t)((b*Sq + t + 1)*Nq + k)*Fq + f];
        g_bh[(size_t)k*NPAD + b*CHW + f] = __float2half_rn(v);
    }
}

// ===================== MMA decoder (fp16, XG fp16, occ-2) =====================
#define DW_ST 264
#define DA_ST 72
#define DXH   264
#define DD_ST 40
#define DS_W  0
#define DS_A  (DS_W + 64*DW_ST*2)           // 33792
#define DS_XG (DS_A + 64*DA_ST*2)           // 43008
#define DS_D1 (DS_XG + 64*DXH*2)            // 76800
#define DS_RED (DS_D1 + 64*DD_ST*2)         // 81920
#define DS_BB  (DS_RED + 64*8*4)            // 83968
#define DS_B1  (DS_BB + 256*4)              // 84992
#define DS_D2  (DS_B1 + 32*4)               // 85120
#define DS_TOT (DS_D2 + 32*4)               // 85248

__device__ __forceinline__ void dec_gemm_k64(float acc[2][8][4], uint32_t sb,
        int wm, int wn, int lrow, int lhalf){
    #pragma unroll
    for(int k16=0;k16<4;k16++){
        uint32_t ah[2][4];
        #pragma unroll
        for(int mt=0;mt<2;mt++){
            int row = wm*32 + mt*16 + lrow;
            uint32_t off = (uint32_t)row*(DA_ST*2) + (uint32_t)(k16*32 + lhalf*16);
            ldsm4(ah[mt], sb + DS_A + off);
        }
        uint32_t bh[4][4];
        #pragma unroll
        for(int nt16=0;nt16<4;nt16++){
            int k = k16*16 + lrow;
            uint32_t off = (uint32_t)k*(DW_ST*2)
                + (uint32_t)(wn*128 + nt16*32 + lhalf*16);
            ldsm4t(bh[nt16], sb + DS_W + off);
        }
        #pragma unroll
        for(int mt=0;mt<2;mt++)
            #pragma unroll
            for(int nt16=0;nt16<4;nt16++)
                #pragma unroll
                for(int h8=0;h8<2;h8++){
                    mma16816h(acc[mt][nt16*2 + h8], ah[mt],
                              bh[nt16][2*h8], bh[nt16][2*h8+1]);
                }
    }
}

__global__ __launch_bounds__(256,2) void k_dec_mma(
        const float* __restrict__ bd1, const float* __restrict__ D2,
        const float* __restrict__ bd2, float* __restrict__ out)
{
    extern __shared__ char smd[];
    const uint32_t sb = smem_u32(smd);
    __half* WS = (__half*)(smd + DS_W);
    __half* AS = (__half*)(smd + DS_A);
    __half* XG = (__half*)(smd + DS_XG);
    __half* D1S16 = (__half*)(smd + DS_D1);
    float* RED = (float*)(smd + DS_RED);
    float* BB  = (float*)(smd + DS_BB);
    float* B1S = (float*)(smd + DS_B1);
    float* D2S = (float*)(smd + DS_D2);
    const int tid = threadIdx.x, lane = tid & 31, wid = tid >> 5;
    const int r0 = blockIdx.x * 64;
    const int lrow = lane & 15, lhalf = lane >> 4;
    const int q = lane & 3, rql = lane >> 2;
    const int wm = wid & 1, wn = wid >> 1;
    const int hm = wid >> 1, hn = wid & 1;

    for(int idx=tid; idx<64*64; idx+=256){
        int row = idx >> 6, k = idx & 63;
        AS[row*DA_ST + k] = __float2half_rn(g_h[(size_t)(r0+row)*64 + k]);
    }
    for(int idx=tid; idx<64*256; idx+=256){
        int k = idx >> 8, c = idx & 255;
        WS[k*DW_ST + c] = g_dwih[idx];
    }
    {
        const __half zh = __float2half_rn(0.f);
        for(int idx=tid; idx<64*DD_ST; idx+=256){
            int k = idx / DD_ST, c = idx - k*DD_ST;
            D1S16[idx] = (c < 32) ? g_d1[k*32 + c] : zh;
        }
    }
    if(tid < 256) BB[tid] = g_dbb[tid];
    if(tid < 32){ B1S[tid] = bd1[tid]; D2S[tid] = D2[tid]; }
    __syncthreads();

    {
        float acc[2][8][4];
        #pragma unroll
        for(int mt=0;mt<2;mt++)
            #pragma unroll
            for(int nt=0;nt<8;nt++){
                int c0 = wn*64 + nt*8 + q*2;
                acc[mt][nt][0] = BB[c0];   acc[mt][nt][1] = BB[c0+1];
                acc[mt][nt][2] = BB[c0];   acc[mt][nt][3] = BB[c0+1];
            }
        dec_gemm_k64(acc, sb, wm, wn, lrow, lhalf);
        #pragma unroll
        for(int mt=0;mt<2;mt++)
            #pragma unroll
            for(int nt=0;nt<8;nt++){
                int r = wm*32 + mt*16 + rql;
                int c0 = wn*64 + nt*8 + q*2;
                *(__half2*)(XG + r*DXH + c0) =
                    __halves2half2(__float2half_rn(acc[mt][nt][0]),
                                   __float2half_rn(acc[mt][nt][1]));
                *(__half2*)(XG + (r+8)*DXH + c0) =
                    __halves2half2(__float2half_rn(acc[mt][nt][2]),
                                   __float2half_rn(acc[mt][nt][3]));
            }
    }
    __syncthreads();
    for(int idx=tid; idx<64*256; idx+=256){
        int k = idx >> 8, c = idx & 255;
        WS[k*DW_ST + c] = g_dwhh[idx];
    }
    __syncthreads();

    float cst[2][8];
    #pragma unroll
    for(int mt=0;mt<2;mt++)
        #pragma unroll
        for(int nt=0;nt<8;nt++) cst[mt][nt] = 0.f;
    const float bd2v = bd2[0];

    for(int s=0; s<Sq; s++){
        float acc[2][8][4];
        #pragma unroll
        for(int mt=0;mt<2;mt++)
            #pragma unroll
            for(int nt=0;nt<8;nt++){
                int r = wm*32 + mt*16 + rql;
                int c0 = wn*64 + nt*8 + q*2;
                float2 lo = __half22float2(*(const __half2*)(XG + r*DXH + c0));
                float2 hi = __half22float2(*(const __half2*)(XG + (r+8)*DXH + c0));
                acc[mt][nt][0] = lo.x; acc[mt][nt][1] = lo.y;
                acc[mt][nt][2] = hi.x; acc[mt][nt][3] = hi.y;
            }
        if(s > 0) dec_gemm_k64(acc, sb, wm, wn, lrow, lhalf);
        __syncthreads();

        #pragma unroll
        for(int mt=0;mt<2;mt++){
            #pragma unroll
            for(int nt=0;nt<8;nt++){
                float d0 = acc[mt][nt][0], d1 = acc[mt][nt][1];
                float d2 = acc[mt][nt][2], d3 = acc[mt][nt][3];
                float e0 = __shfl_xor_sync(0xffffffffu, d0, 1);
                float e1 = __shfl_xor_sync(0xffffffffu, d1, 1);
                float e2 = __shfl_xor_sync(0xffffffffu, d2, 1);
                float e3 = __shfl_xor_sync(0xffffffffu, d3, 1);
                float iv, fv, gv, ov;
                if((lane & 1) == 0){ iv = d0; fv = d1; gv = e0; ov = e1; }
                else               { iv = e2; fv = e3; gv = d2; ov = d3; }
                float cc = sigf(fv)*cst[mt][nt] + sigf(iv)*tanhf(gv);
                cst[mt][nt] = cc;
                float hh = sigf(ov)*tanhf(cc);
                int row = wm*32 + mt*16 + rql + ((lane & 1) << 3);
                int hc  = wn*16 + nt*2 + (q >> 1);
                AS[row*DA_ST + hc] = __float2half_rn(hh);
            }
        }
        __syncthreads();

        float u[2][4];
        #pragma unroll
        for(int h8=0;h8<2;h8++){
            int c0 = hn*16 + h8*8 + q*2;
            u[h8][0] = B1S[c0]; u[h8][1] = B1S[c0+1];
            u[h8][2] = B1S[c0]; u[h8][3] = B1S[c0+1];
        }
        #pragma unroll
        for(int k16=0;k16<4;k16++){
            uint32_t a2h[4];
            {
                int row = hm*16 + lrow;
                uint32_t off = (uint32_t)row*(DA_ST*2) + (uint32_t)(k16*32 + lhalf*16);
                ldsm4(a2h, sb + DS_A + off);
            }
            uint32_t dh[4];
            {
                int k = k16*16 + lrow;
                uint32_t off = (uint32_t)k*(DD_ST*2) + (uint32_t)(hn*32 + lhalf*16);
                ldsm4t(dh, sb + DS_D1 + off);
            }
            #pragma unroll
            for(int h8=0;h8<2;h8++){
                mma16816h(u[h8], a2h, dh[2*h8], dh[2*h8+1]);
            }
        }
        float pr = 0.f, pr8 = 0.f;
        #pragma unroll
        for(int h8=0;h8<2;h8++){
            int c0 = hn*16 + h8*8 + q*2;
            pr  += fmaxf(u[h8][0],0.f)*D2S[c0] + fmaxf(u[h8][1],0.f)*D2S[c0+1];
            pr8 += fmaxf(u[h8][2],0.f)*D2S[c0] + fmaxf(u[h8][3],0.f)*D2S[c0+1];
        }
        int hr = hm*16 + rql;
        RED[hr*8 + hn*4 + q]     = pr;
        RED[(hr+8)*8 + hn*4 + q] = pr8;
        __syncthreads();
        if(tid < 64){
            float ssum = bd2v;
            #pragma unroll
            for(int e=0;e<8;e++) ssum += RED[tid*8 + e];
            out[ZOUT + (size_t)(r0 + tid)*Sq + s] = ssum;
        }
    }
}

// ------------------------------------------------------------------
extern "C" void kernel_launch(void* const* d_in, const int* in_sizes, int n_in,
                              void* d_out, int out_size)
{
    const float* X    = (const float*)d_in[0];
    const float* adj  = (const float*)d_in[1];
    const float* se   = (const float*)d_in[2];
    const float* W1   = (const float*)d_in[3];
    const float* b1   = (const float*)d_in[4];
    const float* W2   = (const float*)d_in[5];
    const float* b2   = (const float*)d_in[6];
    const float* W_ih = (const float*)d_in[7];
    const float* W_hh = (const float*)d_in[8];
    const float* b_ih = (const float*)d_in[9];
    const float* b_hh = (const float*)d_in[10];
    const float* D1   = (const float*)d_in[11];
    const float* bd1  = (const float*)d_in[12];
    const float* D2   = (const float*)d_in[13];
    const float* bd2  = (const float*)d_in[14];
    float* out = (float*)d_out;

    const int smem_mma = 4*MSTAGE;                                   // 49152
    cudaFuncSetAttribute(k_mma,       cudaFuncAttributeMaxDynamicSharedMemorySize, smem_mma);
    cudaFuncSetAttribute(k_gates_mma, cudaFuncAttributeMaxDynamicSharedMemorySize, GSM_TOT);
    cudaFuncSetAttribute(k_dec_mma,   cudaFuncAttributeMaxDynamicSharedMemorySize, DS_TOT);

    // launch order: k_mma is the 4th launch -> captured by ncu
    k_prep_adj<<<(int)((Nq*(size_t)Nq)/256), 256>>>(adj);
    k_prep_w<<<144, 256>>>(W1, W2, W_ih, W_hh, b_ih, b_hh, D1);
    k_prep_bh<<<NH/256 + (32*4096)/256, 256>>>(se, X);
    for(int t=0; t<Sq; t++){
        k_mma<<<dim3(Nq/128, 9), 256, smem_mma>>>();
        k_gates_mma<<<dim3(Nq/128, Bq), 256, GSM_TOT>>>(b1, b2);
        int cgrid = CELL_BLOCKS + (t+1 < Sq ? (32*4096)/256 : 0);
        k_cell_catx<<<cgrid, 256>>>(se, X, out, t);
    }
    k_dec_mma<<<(Bq*Nq)/64, 256, DS_TOT>>>(bd1, D2, bd2, out);
}

// round 17
// speedup vs baseline: 1.4177x; 1.1469x over previous
#include <cuda_runtime.h>
#include <cuda_bf16.h>
#include <cuda_fp16.h>
#include <math.h>
#include <stdint.h>

#define Bq 8
#define Sq 12
#define Nq 4096
#define Fq 4
#define Hq 64
#define CHW 68                    // F + H
#define NCOL 544                  // logical diffusion cols (b*68+f)
#define AST 1024                  // g_a row stride (fp16): b*128+f, pads zero
#define NPAD 576                  // padded B columns
#define NH  (Nq*Hq)               // 262144
#define N3H (Nq*3*Hq)             // 786432
#define ZOUT ((size_t)Bq*NH)      // offset of recon in output
#define ASCALE 2048.0f
#define AINV   (1.0f/2048.0f)

// -------- persistent scratch (device globals; no allocation) --------
__device__ float g_h[Bq*NH];                        // h_last only (written at t=11)
__device__ __align__(16) __half g_a[(size_t)Nq*AST]; // diffusion out fp16 [m][b*128+f]
__device__ __align__(16) __half g_gate[Bq*N3H];     // sigmoid(gc1) torch-flat, fp16
__device__ __align__(16) __half g_tconv[Bq*NH];     // tanh(gc2), fp16
__device__ __align__(16) __half g_ah[(size_t)Nq*Nq];           // adj*2^11 (fp16)
__device__ __align__(16) __half g_bh[(size_t)Nq*NPAD];         // catT fp16 [k][col]
__device__ __align__(16) __half g_w[80*256];                   // W1|W2 fp16 [k][ch]
// decoder fp16 weights (column-permuted: col = hc*4 + gate)
__device__ __align__(16) __half g_dwih[64*256];
__device__ __align__(16) __half g_dwhh[64*256];
__device__ __align__(16) __half g_d1[64*32];
__device__ float g_dbb[256];                        // permuted b_ih+b_hh

// ---- fast activations: single-MUFU tanh.approx (error ~2^-11, fp16 class) ----
__device__ __forceinline__ float tanh_fast(float x){
    float y;
    asm("tanh.approx.f32 %0, %1;" : "=f"(y) : "f"(x));
    return y;
}
__device__ __forceinline__ float sigf(float x){
    return fmaf(tanh_fast(0.5f*x), 0.5f, 0.5f);
}

// ---- warp MMA helpers ----
__device__ __forceinline__ uint32_t smem_u32(const void* p) {
    uint32_t a;
    asm("{ .reg .u64 t; cvta.to.shared.u64 t, %1; cvt.u32.u64 %0, t; }"
        : "=r"(a) : "l"(p));
    return a;
}
__device__ __forceinline__ void cpasync16(uint32_t dst, const void* src){
    asm volatile("cp.async.cg.shared.global [%0], [%1], 16;"
                 :: "r"(dst), "l"(src) : "memory");
}
__device__ __forceinline__ void ldsm4(uint32_t r[4], uint32_t addr){
    asm volatile("ldmatrix.sync.aligned.m8n8.x4.shared.b16 {%0,%1,%2,%3}, [%4];"
                 : "=r"(r[0]), "=r"(r[1]), "=r"(r[2]), "=r"(r[3]) : "r"(addr));
}
__device__ __forceinline__ void ldsm4t(uint32_t r[4], uint32_t addr){
    asm volatile("ldmatrix.sync.aligned.m8n8.x4.trans.shared.b16 {%0,%1,%2,%3}, [%4];"
                 : "=r"(r[0]), "=r"(r[1]), "=r"(r[2]), "=r"(r[3]) : "r"(addr));
}
// fp16 MMA
__device__ __forceinline__ void mma16816h(float d[4], const uint32_t a[4],
                                          uint32_t b0, uint32_t b1){
    asm volatile(
        "mma.sync.aligned.m16n8k16.row.col.f32.f16.f16.f32 "
        "{%0,%1,%2,%3}, {%4,%5,%6,%7}, {%8,%9}, {%0,%1,%2,%3};"
        : "+f"(d[0]), "+f"(d[1]), "+f"(d[2]), "+f"(d[3])
        : "r"(a[0]), "r"(a[1]), "r"(a[2]), "r"(a[3]), "r"(b0), "r"(b1));
}

// ===================== one-time prep (3 kernels; k_mma is launch #4) =====================
__global__ void k_prep_adj(const float* __restrict__ adj){
    size_t i = (size_t)blockIdx.x*256 + threadIdx.x;   // Nq*Nq exactly
    g_ah[i] = __float2half_rn(adj[i] * ASCALE);
}

__global__ void k_prep_w(const float* __restrict__ W1, const float* __restrict__ W2,
                         const float* __restrict__ W_ih, const float* __restrict__ W_hh,
                         const float* __restrict__ b_ih, const float* __restrict__ b_hh,
                         const float* __restrict__ D1){
    if(blockIdx.x < 80){
        int idx = blockIdx.x*256 + threadIdx.x;
        int f = idx >> 8, ch = idx & 255;
        float v = 0.f;
        if(f < 68) v = (ch < 192) ? W1[f*192 + ch] : W2[f*64 + ch - 192];
        g_w[idx] = __float2half_rn(v);
    } else {
        int idx = (blockIdx.x - 80)*256 + threadIdx.x;  // 64*256
        int k = idx >> 8, c = idx & 255;
        int hc = c >> 2, gate = c & 3;
        g_dwih[idx] = __float2half_rn(W_ih[(gate*64 + hc)*64 + k]);
        g_dwhh[idx] = __float2half_rn(W_hh[(gate*64 + hc)*64 + k]);
        if(idx < 64*32) g_d1[idx] = __float2half_rn(D1[idx]);
        if(idx < 256){
            int g2 = idx & 3, h2 = idx >> 2;
            g_dbb[idx] = b_ih[g2*64 + h2] + b_hh[g2*64 + h2];
        }
    }
}

__global__ void k_prep_bh(const float* __restrict__ se, const float* __restrict__ X){
    if(blockIdx.x < NH/256){
        int j = blockIdx.x*256 + threadIdx.x;   // NH exactly
        int n = j >> 6, hc = j & 63;
        __half hv = __float2half_rn(se[j]);
        #pragma unroll
        for(int b=0;b<Bq;b++)
            g_bh[(size_t)n*NPAD + b*CHW + 4 + hc] = hv;
    } else {
        int i = (blockIdx.x - NH/256)*256 + threadIdx.x;   // 32*4096 exactly
        int b = i >> 14, f = (i >> 12) & 3, k = i & 4095;
        float v = X[(size_t)(b*Sq*Nq + k)*Fq + f];  // t = 0
        g_bh[(size_t)k*NPAD + b*CHW + f] = __float2half_rn(v);
    }
}

// ===================== HMMA GEMM (encoder diffusion, fp16) =====================
#define MSTAGE 12288
#define MA_OFF 0
#define MB_OFF 8192

__device__ __forceinline__ void mma_load_stage(uint32_t dbase, int s, int kt,
                                               int m0, int n0, int tid){
    const uint32_t sb = dbase + (uint32_t)s*MSTAGE;
    const int k0 = kt*32;
    #pragma unroll
    for(int it=0; it<2; it++){
        int i = tid + it*256;
        int row = i >> 2, c = i & 3;
        const __half* src = g_ah + ((size_t)(m0+row) << 12) + k0 + c*8;
        uint32_t dst = sb + MA_OFF
            + (uint32_t)row*64 + (uint32_t)((c ^ ((row>>1)&3))<<4);
        cpasync16(dst, src);
    }
    {
        int i = tid;
        int row = i >> 3, c = i & 7;
        const __half* src = g_bh + (size_t)(k0+row)*NPAD + n0 + c*8;
        uint32_t dst = sb + MB_OFF
            + (uint32_t)row*128 + (uint32_t)((c ^ (row&7))<<4);
        cpasync16(dst, src);
    }
}

__global__ __launch_bounds__(256,2) void k_mma(){
    extern __shared__ char dyn[];
    const uint32_t dbase = smem_u32(dyn);
    const int tid = threadIdx.x;
    const int lane = tid & 31, wid = tid >> 5;
    const int warp_m = wid & 3, warp_n = wid >> 2;
    const int m0 = blockIdx.x * 128;
    const int n0 = blockIdx.y * 64;
    const int lrow = lane & 15, lhalf = lane >> 4;

    float acc[2][4][4];
    #pragma unroll
    for(int mt=0;mt<2;mt++)
        #pragma unroll
        for(int nt=0;nt<4;nt++)
            #pragma unroll
            for(int q=0;q<4;q++) acc[mt][nt][q] = 0.f;

    mma_load_stage(dbase, 0, 0, m0, n0, tid);
    asm volatile("cp.async.commit_group;" ::: "memory");
    mma_load_stage(dbase, 1, 1, m0, n0, tid);
    asm volatile("cp.async.commit_group;" ::: "memory");
    mma_load_stage(dbase, 2, 2, m0, n0, tid);
    asm volatile("cp.async.commit_group;" ::: "memory");

    for(int kt=0; kt<128; kt++){
        if(kt < 126)      { asm volatile("cp.async.wait_group 2;" ::: "memory"); }
        else if(kt == 126){ asm volatile("cp.async.wait_group 1;" ::: "memory"); }
        else              { asm volatile("cp.async.wait_group 0;" ::: "memory"); }
        __syncthreads();

        if(kt + 3 < 128){
            mma_load_stage(dbase, (kt+3)&3, kt+3, m0, n0, tid);
            asm volatile("cp.async.commit_group;" ::: "memory");
        }

        const uint32_t sb = dbase + (uint32_t)(kt&3)*MSTAGE;
        #pragma unroll
        for(int k16=0; k16<2; k16++){
            uint32_t ah[2][4];
            #pragma unroll
            for(int mt=0; mt<2; mt++){
                int row = warp_m*32 + mt*16 + lrow;
                int c = k16*2 + lhalf;
                uint32_t off = (uint32_t)row*64 + (uint32_t)((c ^ ((row>>1)&3))<<4);
                ldsm4(ah[mt], sb + MA_OFF + off);
            }
            uint32_t bh[2][4];
            #pragma unroll
            for(int nt16=0; nt16<2; nt16++){
                int k = k16*16 + lrow;
                int c = warp_n*4 + nt16*2 + lhalf;
                uint32_t off = (uint32_t)k*128 + (uint32_t)((c ^ (k&7))<<4);
                ldsm4t(bh[nt16], sb + MB_OFF + off);
            }
            #pragma unroll
            for(int mt=0; mt<2; mt++)
                #pragma unroll
                for(int nt16=0; nt16<2; nt16++)
                    #pragma unroll
                    for(int h8=0; h8<2; h8++){
                        mma16816h(acc[mt][nt16*2 + h8], ah[mt],
                                  bh[nt16][2*h8], bh[nt16][2*h8+1]);
                    }
        }
    }

    #pragma unroll
    for(int mt=0; mt<2; mt++){
        #pragma unroll
        for(int nt=0; nt<4; nt++){
            int col = n0 + warp_n*32 + nt*8 + (lane&3)*2;
            if(col < NCOL){
                int bb = col / 68, ff = col - bb*68;
                int colA = bb*128 + ff;                 // packed g_a layout
                int r0 = m0 + warp_m*32 + mt*16 + (lane>>2);
                __half2 h0 = __halves2half2(__float2half_rn(acc[mt][nt][0]*AINV),
                                            __float2half_rn(acc[mt][nt][1]*AINV));
                __half2 h1 = __halves2half2(__float2half_rn(acc[mt][nt][2]*AINV),
                                            __float2half_rn(acc[mt][nt][3]*AINV));
                *(__half2*)(g_a + (size_t)r0*AST + colA)     = h0;
                *(__half2*)(g_a + (size_t)(r0+8)*AST + colA) = h1;
            }
        }
    }
}

// ===================== gates GEMM + activations (fp16, z-merged) =====================
#define GA_B 272
#define GW_B 272
#define GSM_A 0
#define GSM_W0 (128*GA_B)                   // 34816
#define GSM_W1 (GSM_W0 + 80*GW_B)           // 56576
#define GSM_BC (GSM_W1 + 80*GW_B)           // 78336
#define GSM_TOT (GSM_BC + 256*4)            // 79360

__global__ __launch_bounds__(256,2) void k_gates_mma(
        const float* __restrict__ b1, const float* __restrict__ b2){
    extern __shared__ char smg[];
    const uint32_t sb = smem_u32(smg);
    float* bc = (float*)(smg + GSM_BC);
    const int tid = threadIdx.x, lane = tid & 31, wid = tid >> 5;
    const int warp_m = wid & 3, warp_n = wid >> 2;
    const int m0 = blockIdx.x * 128;
    const int b  = blockIdx.y;
    const int lrow = lane & 15, lhalf = lane >> 4;

    #pragma unroll
    for(int it=0; it<8; it++){
        int i = tid + it*256;
        int row = i >> 4, c = i & 15;
        const __half* src = g_a + (size_t)(m0+row)*AST + b*128 + c*8;
        cpasync16(sb + GSM_A + (uint32_t)row*GA_B + (uint32_t)c*16, src);
    }
    #pragma unroll
    for(int it=0; it<10; it++){
        int z2 = it / 5;
        int i = tid + (it - z2*5)*256;
        int f = i >> 4, c = i & 15;
        const __half* src = g_w + f*256 + z2*128 + c*8;
        cpasync16(sb + (z2 ? GSM_W1 : GSM_W0)
                  + (uint32_t)f*GW_B + (uint32_t)c*16, src);
    }
    asm volatile("cp.async.commit_group;" ::: "memory");
    {
        int ch = tid;   // 0..255
        bc[ch] = (ch < 192) ? b1[ch] : b2[ch - 192];
    }
    asm volatile("cp.async.wait_group 0;" ::: "memory");
    __syncthreads();

    #pragma unroll
    for(int z = 0; z < 2; z++){
        const uint32_t wbase = sb + (z ? GSM_W1 : GSM_W0);
        float acc[2][8][4];
        #pragma unroll
        for(int mt=0;mt<2;mt++)
            #pragma unroll
            for(int nt=0;nt<8;nt++)
                #pragma unroll
                for(int q=0;q<4;q++) acc[mt][nt][q] = 0.f;

        #pragma unroll
        for(int k16=0; k16<5; k16++){
            uint32_t ah[2][4];
            #pragma unroll
            for(int mt=0; mt<2; mt++){
                int row = warp_m*32 + mt*16 + lrow;
                uint32_t off = (uint32_t)row*GA_B + (uint32_t)(k16*32 + lhalf*16);
                ldsm4(ah[mt], sb + GSM_A + off);
            }
            uint32_t bh[4][4];
            #pragma unroll
            for(int nt16=0; nt16<4; nt16++){
                int k = k16*16 + lrow;
                uint32_t off = (uint32_t)k*GW_B
                    + (uint32_t)(warp_n*128 + nt16*32 + lhalf*16);
                ldsm4t(bh[nt16], wbase + off);
            }
            #pragma unroll
            for(int mt=0; mt<2; mt++)
                #pragma unroll
                for(int nt16=0; nt16<4; nt16++)
                    #pragma unroll
                    for(int h8=0; h8<2; h8++){
                        mma16816h(acc[mt][nt16*2 + h8], ah[mt],
                                  bh[nt16][2*h8], bh[nt16][2*h8+1]);
                    }
        }

        #pragma unroll
        for(int mt=0; mt<2; mt++){
            #pragma unroll
            for(int nt=0; nt<8; nt++){
                int col = warp_n*64 + nt*8 + (lane&3)*2;
                int ch  = z*128 + col;
                float bb0 = bc[ch], bb1 = bc[ch+1];
                int r0 = m0 + warp_m*32 + mt*16 + (lane>>2);
                #pragma unroll
                for(int hf=0; hf<2; hf++){
                    int node = r0 + 8*hf;
                    float v0 = acc[mt][nt][2*hf]   + bb0;
                    float v1 = acc[mt][nt][2*hf+1] + bb1;
                    if(ch < 192){
                        __half2 o = __halves2half2(__float2half_rn(sigf(v0)),
                                                   __float2half_rn(sigf(v1)));
                        *(__half2*)(g_gate + (size_t)b*N3H + (size_t)node*192 + ch) = o;
                    }else{
                        __half2 o = __halves2half2(__float2half_rn(tanh_fast(v0)),
                                                   __float2half_rn(tanh_fast(v1)));
                        *(__half2*)(g_tconv + (size_t)b*NH + (size_t)node*64 + (ch-192)) = o;
                    }
                }
            }
        }
    }
}

// -------- fused: LSTM cell (2 elems/thread) + catT X cols for t+1; z-out at t=11 --------
#define CELL_BLOCKS ((Bq*NH)/512)
__global__ void k_cell_catx(const float* __restrict__ se, const float* __restrict__ X,
                            float* __restrict__ out, int t){
    if(blockIdx.x < CELL_BLOCKS){
        int idx = (blockIdx.x*256 + threadIdx.x)*2;   // even, covers Bq*NH
        int b = idx >> 18;
        int j = idx & (NH-1);
        const __half* gg = g_gate + (size_t)b*N3H;
        __half2 f2 = *(const __half2*)(gg + j);
        __half2 i2 = *(const __half2*)(gg + NH + j);
        __half2 o2 = *(const __half2*)(gg + 2*NH + j);
        __half2 t2 = *(const __half2*)(g_tconv + (size_t)b*NH + j);
        float2 se2 = *(const float2*)(se + j);
        float c0 = __low2float(f2)*se2.x  + __low2float(i2)*__low2float(t2);
        float c1 = __high2float(f2)*se2.y + __high2float(i2)*__high2float(t2);
        float h0 = __low2float(o2)  * tanh_fast(c0);
        float h1 = __high2float(o2) * tanh_fast(c1);
        int n = j >> 6, hc = j & 63;
        *(__half2*)(g_bh + (size_t)n*NPAD + b*CHW + 4 + hc) =
            __halves2half2(__float2half_rn(h0), __float2half_rn(h1));
        if(t == Sq-1){
            float2 hv; hv.x = h0; hv.y = h1;
            *(float2*)(g_h + idx) = hv;
            *(float2*)(out + idx) = hv;
        }
    } else {
        int i = (blockIdx.x - CELL_BLOCKS)*256 + threadIdx.x;  // 32*4096
        int b = i >> 14, f = (i >> 12) & 3, k = i & 4095;
        float v = X[(size_t)((b*Sq + t + 1)*Nq + k)*Fq + f];
        g_bh[(size_t)k*NPAD + b*CHW + f] = __float2half_rn(v);
    }
}

// ===================== MMA decoder (fp16, XG fp16, occ-2) =====================
#define DW_ST 264
#define DA_ST 72
#define DXH   264
#define DD_ST 40
#define DS_W  0
#define DS_A  (DS_W + 64*DW_ST*2)           // 33792
#define DS_XG (DS_A + 64*DA_ST*2)           // 43008
#define DS_D1 (DS_XG + 64*DXH*2)            // 76800
#define DS_RED (DS_D1 + 64*DD_ST*2)         // 81920
#define DS_BB  (DS_RED + 64*8*4)            // 83968
#define DS_B1  (DS_BB + 256*4)              // 84992
#define DS_D2  (DS_B1 + 32*4)               // 85120
#define DS_TOT (DS_D2 + 32*4)               // 85248

__device__ __forceinline__ void dec_gemm_k64(float acc[2][8][4], uint32_t sb,
        int wm, int wn, int lrow, int lhalf){
    #pragma unroll
    for(int k16=0;k16<4;k16++){
        uint32_t ah[2][4];
        #pragma unroll
        for(int mt=0;mt<2;mt++){
            int row = wm*32 + mt*16 + lrow;
            uint32_t off = (uint32_t)row*(DA_ST*2) + (uint32_t)(k16*32 + lhalf*16);
            ldsm4(ah[mt], sb + DS_A + off);
        }
        uint32_t bh[4][4];
        #pragma unroll
        for(int nt16=0;nt16<4;nt16++){
            int k = k16*16 + lrow;
            uint32_t off = (uint32_t)k*(DW_ST*2)
                + (uint32_t)(wn*128 + nt16*32 + lhalf*16);
            ldsm4t(bh[nt16], sb + DS_W + off);
        }
        #pragma unroll
        for(int mt=0;mt<2;mt++)
            #pragma unroll
            for(int nt16=0;nt16<4;nt16++)
                #pragma unroll
                for(int h8=0;h8<2;h8++){
                    mma16816h(acc[mt][nt16*2 + h8], ah[mt],
                              bh[nt16][2*h8], bh[nt16][2*h8+1]);
                }
    }
}

__global__ __launch_bounds__(256,2) void k_dec_mma(
        const float* __restrict__ bd1, const float* __restrict__ D2,
        const float* __restrict__ bd2, float* __restrict__ out)
{
    extern __shared__ char smd[];
    const uint32_t sb = smem_u32(smd);
    __half* WS = (__half*)(smd + DS_W);
    __half* AS = (__half*)(smd + DS_A);
    __half* XG = (__half*)(smd + DS_XG);
    __half* D1S16 = (__half*)(smd + DS_D1);
    float* RED = (float*)(smd + DS_RED);
    float* BB  = (float*)(smd + DS_BB);
    float* B1S = (float*)(smd + DS_B1);
    float* D2S = (float*)(smd + DS_D2);
    const int tid = threadIdx.x, lane = tid & 31, wid = tid >> 5;
    const int r0 = blockIdx.x * 64;
    const int lrow = lane & 15, lhalf = lane >> 4;
    const int q = lane & 3, rql = lane >> 2;
    const int wm = wid & 1, wn = wid >> 1;
    const int hm = wid >> 1, hn = wid & 1;

    for(int idx=tid; idx<64*64; idx+=256){
        int row = idx >> 6, k = idx & 63;
        AS[row*DA_ST + k] = __float2half_rn(g_h[(size_t)(r0+row)*64 + k]);
    }
    for(int idx=tid; idx<64*256; idx+=256){
        int k = idx >> 8, c = idx & 255;
        WS[k*DW_ST + c] = g_dwih[idx];
    }
    {
        const __half zh = __float2half_rn(0.f);
        for(int idx=tid; idx<64*DD_ST; idx+=256){
            int k = idx / DD_ST, c = idx - k*DD_ST;
            D1S16[idx] = (c < 32) ? g_d1[k*32 + c] : zh;
        }
    }
    if(tid < 256) BB[tid] = g_dbb[tid];
    if(tid < 32){ B1S[tid] = bd1[tid]; D2S[tid] = D2[tid]; }
    __syncthreads();

    {
        float acc[2][8][4];
        #pragma unroll
        for(int mt=0;mt<2;mt++)
            #pragma unroll
            for(int nt=0;nt<8;nt++){
                int c0 = wn*64 + nt*8 + q*2;
                acc[mt][nt][0] = BB[c0];   acc[mt][nt][1] = BB[c0+1];
                acc[mt][nt][2] = BB[c0];   acc[mt][nt][3] = BB[c0+1];
            }
        dec_gemm_k64(acc, sb, wm, wn, lrow, lhalf);
        #pragma unroll
        for(int mt=0;mt<2;mt++)
            #pragma unroll
            for(int nt=0;nt<8;nt++){
                int r = wm*32 + mt*16 + rql;
                int c0 = wn*64 + nt*8 + q*2;
                *(__half2*)(XG + r*DXH + c0) =
                    __halves2half2(__float2half_rn(acc[mt][nt][0]),
                                   __float2half_rn(acc[mt][nt][1]));
                *(__half2*)(XG + (r+8)*DXH + c0) =
                    __halves2half2(__float2half_rn(acc[mt][nt][2]),
                                   __float2half_rn(acc[mt][nt][3]));
            }
    }
    __syncthreads();
    for(int idx=tid; idx<64*256; idx+=256){
        int k = idx >> 8, c = idx & 255;
        WS[k*DW_ST + c] = g_dwhh[idx];
    }
    __syncthreads();

    float cst[2][8];
    #pragma unroll
    for(int mt=0;mt<2;mt++)
        #pragma unroll
        for(int nt=0;nt<8;nt++) cst[mt][nt] = 0.f;
    const float bd2v = bd2[0];

    for(int s=0; s<Sq; s++){
        float acc[2][8][4];
        #pragma unroll
        for(int mt=0;mt<2;mt++)
            #pragma unroll
            for(int nt=0;nt<8;nt++){
                int r = wm*32 + mt*16 + rql;
                int c0 = wn*64 + nt*8 + q*2;
                float2 lo = __half22float2(*(const __half2*)(XG + r*DXH + c0));
                float2 hi = __half22float2(*(const __half2*)(XG + (r+8)*DXH + c0));
                acc[mt][nt][0] = lo.x; acc[mt][nt][1] = lo.y;
                acc[mt][nt][2] = hi.x; acc[mt][nt][3] = hi.y;
            }
        if(s > 0) dec_gemm_k64(acc, sb, wm, wn, lrow, lhalf);
        __syncthreads();

        #pragma unroll
        for(int mt=0;mt<2;mt++){
            #pragma unroll
            for(int nt=0;nt<8;nt++){
                float d0 = acc[mt][nt][0], d1 = acc[mt][nt][1];
                float d2 = acc[mt][nt][2], d3 = acc[mt][nt][3];
                float e0 = __shfl_xor_sync(0xffffffffu, d0, 1);
                float e1 = __shfl_xor_sync(0xffffffffu, d1, 1);
                float e2 = __shfl_xor_sync(0xffffffffu, d2, 1);
                float e3 = __shfl_xor_sync(0xffffffffu, d3, 1);
                float iv, fv, gv, ov;
                if((lane & 1) == 0){ iv = d0; fv = d1; gv = e0; ov = e1; }
                else               { iv = e2; fv = e3; gv = d2; ov = d3; }
                float cc = sigf(fv)*cst[mt][nt] + sigf(iv)*tanh_fast(gv);
                cst[mt][nt] = cc;
                float hh = sigf(ov)*tanh_fast(cc);
                int row = wm*32 + mt*16 + rql + ((lane & 1) << 3);
                int hc  = wn*16 + nt*2 + (q >> 1);
                AS[row*DA_ST + hc] = __float2half_rn(hh);
            }
        }
        __syncthreads();

        float u[2][4];
        #pragma unroll
        for(int h8=0;h8<2;h8++){
            int c0 = hn*16 + h8*8 + q*2;
            u[h8][0] = B1S[c0]; u[h8][1] = B1S[c0+1];
            u[h8][2] = B1S[c0]; u[h8][3] = B1S[c0+1];
        }
        #pragma unroll
        for(int k16=0;k16<4;k16++){
            uint32_t a2h[4];
            {
                int row = hm*16 + lrow;
                uint32_t off = (uint32_t)row*(DA_ST*2) + (uint32_t)(k16*32 + lhalf*16);
                ldsm4(a2h, sb + DS_A + off);
            }
            uint32_t dh[4];
            {
                int k = k16*16 + lrow;
                uint32_t off = (uint32_t)k*(DD_ST*2) + (uint32_t)(hn*32 + lhalf*16);
                ldsm4t(dh, sb + DS_D1 + off);
            }
            #pragma unroll
            for(int h8=0;h8<2;h8++){
                mma16816h(u[h8], a2h, dh[2*h8], dh[2*h8+1]);
            }
        }
        float pr = 0.f, pr8 = 0.f;
        #pragma unroll
        for(int h8=0;h8<2;h8++){
            int c0 = hn*16 + h8*8 + q*2;
            pr  += fmaxf(u[h8][0],0.f)*D2S[c0] + fmaxf(u[h8][1],0.f)*D2S[c0+1];
            pr8 += fmaxf(u[h8][2],0.f)*D2S[c0] + fmaxf(u[h8][3],0.f)*D2S[c0+1];
        }
        int hr = hm*16 + rql;
        RED[hr*8 + hn*4 + q]     = pr;
        RED[(hr+8)*8 + hn*4 + q] = pr8;
        __syncthreads();
        if(tid < 64){
            float ssum = bd2v;
            #pragma unroll
            for(int e=0;e<8;e++) ssum += RED[tid*8 + e];
            out[ZOUT + (size_t)(r0 + tid)*Sq + s] = ssum;
        }
    }
}

// ------------------------------------------------------------------
extern "C" void kernel_launch(void* const* d_in, const int* in_sizes, int n_in,
                              void* d_out, int out_size)
{
    const float* X    = (const float*)d_in[0];
    const float* adj  = (const float*)d_in[1];
    const float* se   = (const float*)d_in[2];
    const float* W1   = (const float*)d_in[3];
    const float* b1   = (const float*)d_in[4];
    const float* W2   = (const float*)d_in[5];
    const float* b2   = (const float*)d_in[6];
    const float* W_ih = (const float*)d_in[7];
    const float* W_hh = (const float*)d_in[8];
    const float* b_ih = (const float*)d_in[9];
    const float* b_hh = (const float*)d_in[10];
    const float* D1   = (const float*)d_in[11];
    const float* bd1  = (const float*)d_in[12];
    const float* D2   = (const float*)d_in[13];
    const float* bd2  = (const float*)d_in[14];
    float* out = (float*)d_out;

    const int smem_mma = 4*MSTAGE;                                   // 49152
    cudaFuncSetAttribute(k_mma,       cudaFuncAttributeMaxDynamicSharedMemorySize, smem_mma);
    cudaFuncSetAttribute(k_gates_mma, cudaFuncAttributeMaxDynamicSharedMemorySize, GSM_TOT);
    cudaFuncSetAttribute(k_dec_mma,   cudaFuncAttributeMaxDynamicSharedMemorySize, DS_TOT);

    // launch order: k_mma is the 4th launch -> captured by ncu
    k_prep_adj<<<(int)((Nq*(size_t)Nq)/256), 256>>>(adj);
    k_prep_w<<<144, 256>>>(W1, W2, W_ih, W_hh, b_ih, b_hh, D1);
    k_prep_bh<<<NH/256 + (32*4096)/256, 256>>>(se, X);
    for(int t=0; t<Sq; t++){
        k_mma<<<dim3(Nq/128, 9), 256, smem_mma>>>();
        k_gates_mma<<<dim3(Nq/128, Bq), 256, GSM_TOT>>>(b1, b2);
        int cgrid = CELL_BLOCKS + (t+1 < Sq ? (32*4096)/256 : 0);
        k_cell_catx<<<cgrid, 256>>>(se, X, out, t);
    }
    k_dec_mma<<<(Bq*Nq)/64, 256, DS_TOT>>>(bd1, D2, bd2, out);
}